// round 13
// baseline (speedup 1.0000x reference)
#include <cuda_runtime.h>
#include <cuda_bf16.h>
#include <cstdint>

// Problem constants
#define BATCH 64
#define CH    64
#define HH    64
#define WW    64
#define NPOS  1024        // 32*32
#define KPIN  1134        // 42*27 = 9*126
#define KPOUT 1024
#define UP_ELEMS (BATCH*CH*HH*WW)          // 16777216
#define ATTN_ELEMS (BATCH*NPOS*NPOS)       // 67108864

// Scratch (device globals; no allocation)
__device__ float    g_pv[BATCH * CH * NPOS];   // [b][c][n]
__device__ float    g_q[BATCH * NPOS];
__device__ float    g_k[BATCH * NPOS];
__device__ float    g_kc[BATCH * KPIN];
__device__ float    g_kpart[9 * BATCH * NPOS]; // split-K partials [ks][b][m]
__device__ float    g_kmax[BATCH];
__device__ float    g_kmin[BATCH];
__device__ uint32_t g_wuT[256 * 64];           // tf32 bits, [dab][c]

typedef unsigned long long ull;

__device__ __forceinline__ float ex2f(float x) {
    float y;
    asm("ex2.approx.ftz.f32 %0, %1;" : "=f"(y) : "f"(x));
    return y;
}
__device__ __forceinline__ float lg2f(float x) {
    float y;
    asm("lg2.approx.ftz.f32 %0, %1;" : "=f"(y) : "f"(x));
    return y;
}
__device__ __forceinline__ uint32_t tf32r(float x) {
    uint32_t r;
    asm("cvt.rna.tf32.f32 %0, %1;" : "=r"(r) : "f"(x));
    return r;
}
__device__ __forceinline__ void mma_tf32(float& d0, float& d1, float& d2, float& d3,
                                         uint32_t a0, uint32_t a1, uint32_t a2, uint32_t a3,
                                         uint32_t b0, uint32_t b1) {
    asm("mma.sync.aligned.m16n8k8.row.col.f32.tf32.tf32.f32 "
        "{%0,%1,%2,%3}, {%4,%5,%6,%7}, {%8,%9}, {%0,%1,%2,%3};"
        : "+f"(d0), "+f"(d1), "+f"(d2), "+f"(d3)
        : "r"(a0), "r"(a1), "r"(a2), "r"(a3), "r"(b0), "r"(b1));
}
// Pair-permutation within each 8-column group: cols kk and kk+4 become adjacent.
__device__ __forceinline__ int perm8(int k) {
    return (k & ~7) | ((k & 3) << 1) | ((k & 7) >> 2);
}
__device__ __forceinline__ void atomicMaxF(float* addr, float val) {
    if (val >= 0.f) atomicMax(reinterpret_cast<int*>(addr), __float_as_int(val));
    else atomicMin(reinterpret_cast<unsigned int*>(addr),
                   static_cast<unsigned int>(__float_as_int(val)));
}
__device__ __forceinline__ void atomicMinF(float* addr, float val) {
    if (val >= 0.f) atomicMin(reinterpret_cast<int*>(addr), __float_as_int(val));
    else atomicMax(reinterpret_cast<unsigned int*>(addr),
                   static_cast<unsigned int>(__float_as_int(val)));
}

// ---------------------------------------------------------------------------
// Kernel 1: conv2x2(v, wk) -> g_kc[b][ii*27+jj]
// Blocks with ii==0 also stage g_wuT; (ii==0,b==0) inits kmax/kmin.
// ---------------------------------------------------------------------------
__global__ __launch_bounds__(256) void conv_v_kernel(const float* __restrict__ v,
                                                     const float* __restrict__ wk,
                                                     const float* __restrict__ bk,
                                                     const float* __restrict__ wu) {
    __shared__ float vs[64 * 2 * 54];
    __shared__ float wks[256];
    __shared__ float part[8][28];
    int ii = blockIdx.x;
    int b  = blockIdx.y;
    int t  = threadIdx.x;

    if (ii == 0) {
        int idx = b * 256 + t;          // 0..16383, each exactly once
        int dab = idx & 255;
        int c   = idx >> 8;
        g_wuT[dab * 64 + c] = tf32r(wu[c * 256 + dab]);
        if (b == 0 && t < 64) {
            g_kmax[t] = __int_as_float(0xFF800000);   // -inf
            g_kmin[t] = __int_as_float(0x7F800000);   // +inf
        }
    }

    wks[t] = wk[t];
    for (int idx = t; idx < 64 * 2 * 54; idx += 256) {
        int c   = idx / 108;
        int rem = idx - c * 108;
        int a   = rem / 54;
        int col = rem - a * 54;
        vs[idx] = v[((b * 64 + c) * 84 + (2 * ii + a)) * 54 + col];
    }
    __syncthreads();

    if (t < 216) {
        int jj = t % 27;
        int cg = t / 27;
        float acc = 0.f;
        #pragma unroll
        for (int cc = 0; cc < 8; cc++) {
            int c = cg * 8 + cc;
            #pragma unroll
            for (int a = 0; a < 2; a++) {
                float x0 = vs[(c * 2 + a) * 54 + 2 * jj + 0];
                float x1 = vs[(c * 2 + a) * 54 + 2 * jj + 1];
                acc += x0 * wks[c * 4 + a * 2 + 0] + x1 * wks[c * 4 + a * 2 + 1];
            }
        }
        part[cg][jj] = acc;
    }
    __syncthreads();
    if (t < 27) {
        float s = bk[0];
        #pragma unroll
        for (int cg = 0; cg < 8; cg++) s += part[cg][t];
        g_kc[b * KPIN + ii * 27 + t] = s;
    }
}

// ---------------------------------------------------------------------------
// Kernel 2a: split-K partial GEMM.
// grid (16 m-tiles, 9 k-splits), 256 threads, dyn smem = 65024 B.
// ---------------------------------------------------------------------------
__global__ __launch_bounds__(256) void kproj_part_kernel(const float* __restrict__ wproj) {
    extern __shared__ float sm2[];
    float* kcs = sm2;               // [64][127]
    float* ws  = sm2 + 64 * 127;    // [64][127]
    int mt  = blockIdx.x;
    int ksp = blockIdx.y;
    int m0  = mt * 64;
    int k0  = ksp * 126;
    int t   = threadIdx.x;

    for (int idx = t; idx < 64 * 126; idx += 256) {
        int row = idx / 126;
        int jj  = idx - row * 126;
        kcs[row * 127 + jj] = g_kc[row * KPIN + k0 + jj];
        ws[row * 127 + jj]  = wproj[(size_t)(m0 + row) * KPIN + k0 + jj];
    }
    __syncthreads();

    int r  = t >> 4;
    int cc = t & 15;
    int b0 = r * 4;
    int mm0 = cc * 4;

    float acc[4][4];
    #pragma unroll
    for (int i = 0; i < 4; i++)
        #pragma unroll
        for (int j = 0; j < 4; j++) acc[i][j] = 0.f;

    #pragma unroll 3
    for (int jj = 0; jj < 126; jj++) {
        float kv[4], wv_[4];
        #pragma unroll
        for (int v_ = 0; v_ < 4; v_++) kv[v_] = kcs[(b0 + v_) * 127 + jj];
        #pragma unroll
        for (int u = 0; u < 4; u++) wv_[u] = ws[(mm0 + u) * 127 + jj];
        #pragma unroll
        for (int v_ = 0; v_ < 4; v_++)
            #pragma unroll
            for (int u = 0; u < 4; u++) acc[v_][u] += kv[v_] * wv_[u];
    }

    #pragma unroll
    for (int v_ = 0; v_ < 4; v_++)
        #pragma unroll
        for (int u = 0; u < 4; u++)
            g_kpart[((size_t)ksp * 64 + b0 + v_) * NPOS + m0 + mm0 + u] = acc[v_][u];
}

// ---------------------------------------------------------------------------
// Kernel 2b: reduce partials + bias -> g_k; per-b max/min via deterministic
// (order-independent) float-as-int atomics. grid (4, 64), 256 threads.
// ---------------------------------------------------------------------------
__global__ __launch_bounds__(256) void kreduce_kernel(const float* __restrict__ bproj) {
    __shared__ float smax[8], smin[8];
    int b = blockIdx.y, t = threadIdx.x;
    int m = blockIdx.x * 256 + t;
    float s = bproj[m];
    #pragma unroll
    for (int ksp = 0; ksp < 9; ksp++)
        s += g_kpart[((size_t)ksp * 64 + b) * NPOS + m];
    g_k[b * NPOS + m] = s;

    float mx = s, mn = s;
    #pragma unroll
    for (int d = 16; d > 0; d >>= 1) {
        mx = fmaxf(mx, __shfl_xor_sync(0xFFFFFFFF, mx, d));
        mn = fminf(mn, __shfl_xor_sync(0xFFFFFFFF, mn, d));
    }
    if ((t & 31) == 0) { smax[t >> 5] = mx; smin[t >> 5] = mn; }
    __syncthreads();
    if (t < 8) {
        mx = smax[t]; mn = smin[t];
        #pragma unroll
        for (int d = 4; d > 0; d >>= 1) {
            mx = fmaxf(mx, __shfl_xor_sync(0xFF, mx, d));
            mn = fminf(mn, __shfl_xor_sync(0xFF, mn, d));
        }
        if (t == 0) {
            atomicMaxF(&g_kmax[b], mx);
            atomicMinF(&g_kmin[b], mn);
        }
    }
}

// ---------------------------------------------------------------------------
// Kernel 4: conv2x2 of x as tf32 MMA GEMM (im2col at staging).
// Pair-permuted Pn/wvs layout -> fragment loads are LDS.64.
// grid (4 ntile, 64 b), 256 threads. dyn smem = 48384 B.
// ---------------------------------------------------------------------------
__global__ __launch_bounds__(256, 2) void conv_x_kernel(const float* __restrict__ x,
                                                        const float* __restrict__ wq,
                                                        const float* __restrict__ bq,
                                                        const float* __restrict__ wv,
                                                        const float* __restrict__ bv) {
    extern __shared__ uint32_t cxs[];
    uint32_t* Pn  = cxs;                 // 256*38
    uint32_t* wvs = Pn + 9728;           // 64*36
    float*    wqc = reinterpret_cast<float*>(wvs + 2304);   // 32

    int ntile = blockIdx.x;
    int b     = blockIdx.y;
    int t     = threadIdx.x;
    int w     = t >> 5;
    int l     = t & 31;
    int g     = l >> 2;
    int tg    = l & 3;
    int mt    = w & 3;
    int half  = w >> 2;

    float acc[16][4];
    #pragma unroll
    for (int nt = 0; nt < 16; nt++)
        #pragma unroll
        for (int u = 0; u < 4; u++) acc[nt][u] = 0.f;
    float qacc = 0.f;

    for (int chunk = 0; chunk < 8; chunk++) {
        int k0  = chunk * 32;
        int ci0 = chunk * 8;
        __syncthreads();
        #pragma unroll
        for (int s = 0; s < 8; s++) {
            int idx = t + s * 256;
            int co = idx >> 5, kl = idx & 31;
            wvs[co * 36 + perm8(kl)] = tf32r(wv[co * 256 + k0 + kl]);
        }
        if (t < 32) wqc[perm8(t)] = wq[k0 + t];
        #pragma unroll
        for (int s = 0; s < 8; s++) {
            int idx = t + s * 256;
            int cl  = idx >> 8;
            int rem = idx & 255;
            int r   = rem >> 4;
            int c4  = rem & 15;
            float4 xv = *reinterpret_cast<const float4*>(
                &x[(((size_t)b * 64 + ci0 + cl) * 64 + ntile * 16 + r) * 64 + c4 * 4]);
            int n2 = (r >> 1) * 32 + c4 * 2;
            int kb = cl * 4 + (r & 1) * 2;
            int pa = perm8(kb), pb = perm8(kb + 1);
            Pn[n2 * 38 + pa]       = tf32r(xv.x);
            Pn[n2 * 38 + pb]       = tf32r(xv.y);
            Pn[(n2 + 1) * 38 + pa] = tf32r(xv.z);
            Pn[(n2 + 1) * 38 + pb] = tf32r(xv.w);
        }
        __syncthreads();

        {
            const uint32_t* pr = &Pn[t * 38];
            #pragma unroll 8
            for (int k = 0; k < 32; k++)
                qacc = fmaf(wqc[k], __uint_as_float(pr[k]), qacc);
        }

        #pragma unroll
        for (int k8 = 0; k8 < 4; k8++) {
            const uint32_t* ap = &wvs[(mt * 16 + g) * 36 + k8 * 8 + 2 * tg];
            uint2 alo = *reinterpret_cast<const uint2*>(ap);           // (kk, kk+4) row r
            uint2 ahi = *reinterpret_cast<const uint2*>(ap + 8 * 36);  // row r+8
            #pragma unroll
            for (int nt = 0; nt < 16; nt++) {
                const uint32_t* bp =
                    &Pn[(half * 128 + nt * 8 + g) * 38 + k8 * 8 + 2 * tg];
                uint2 bb = *reinterpret_cast<const uint2*>(bp);
                mma_tf32(acc[nt][0], acc[nt][1], acc[nt][2], acc[nt][3],
                         alo.x, ahi.x, alo.y, ahi.y, bb.x, bb.y);
            }
        }
    }

    int c0 = mt * 16 + g;
    float bv0 = bv[c0];
    float bv8 = bv[c0 + 8];
    int nb = ntile * 256 + half * 128;
    #pragma unroll
    for (int nt = 0; nt < 16; nt++) {
        int n = nb + nt * 8 + 2 * tg;
        *reinterpret_cast<float2*>(&g_pv[((size_t)b * 64 + c0) * NPOS + n]) =
            make_float2(acc[nt][0] + bv0, acc[nt][1] + bv0);
        *reinterpret_cast<float2*>(&g_pv[((size_t)b * 64 + c0 + 8) * NPOS + n]) =
            make_float2(acc[nt][2] + bv8, acc[nt][3] + bv8);
    }
    g_q[b * NPOS + ntile * 256 + t] = qacc + bq[0];
}

// ---------------------------------------------------------------------------
// Kernel 5: fused softmax + attn write + tf32 MMA GEMM + ConvTranspose2d.
// 256 m-rows/block, grid (4, 64), 256 threads, dyn smem = 93184 B.
// pvs pair-permuted -> A-frag loads are LDS.64.
// ---------------------------------------------------------------------------
__global__ __launch_bounds__(256, 2) void attn_kernel(float* __restrict__ attn_out,
                                                      int has_attn,
                                                      const float* __restrict__ bu,
                                                      float* __restrict__ up) {
    extern __shared__ float dsm[];
    float*    ks   = dsm;                                      // [1024]
    float*    sLs  = dsm + 1024;                               // [256]
    float*    offs = dsm + 1280;                               // [256]
    uint32_t* pvs  = reinterpret_cast<uint32_t*>(dsm + 1536);  // [64*68]
    float*    es   = dsm + 1536 + 4352;                        // [256*68]
    uint32_t* outS = reinterpret_cast<uint32_t*>(es);          // alias

    const float L2E = 1.4426950408889634f;
    int mt = blockIdx.x;
    int b  = blockIdx.y;
    int m0 = mt * 256;
    int t  = threadIdx.x;
    int w  = t >> 5;
    int l  = t & 31;
    int g  = l >> 2;
    int tg = l & 3;

    for (int n = t; n < NPOS; n += 256) ks[n] = g_k[b * NPOS + n];

    int pv_c  = t >> 6;
    int pv_nn = t & 63;
    int pv_pp = perm8(pv_nn);
    float pvf[16];
    #pragma unroll
    for (int s = 0; s < 16; s++)
        pvf[s] = g_pv[((size_t)b * 64 + (pv_c + s * 4)) * NPOS + pv_nn];

    __syncthreads();

    {
        float s   = g_q[b * NPOS + m0 + t] * 0.03125f;   // 1/sqrt(1024)
        float rm  = (s >= 0.f) ? s * g_kmax[b] : s * g_kmin[b];
        float sL  = s * L2E;
        float rmL = rm * L2E;
        float p0 = 0.f, p1 = 0.f, p2 = 0.f, p3 = 0.f;
        #pragma unroll 4
        for (int n = 0; n < 1024; n += 4) {
            p0 += ex2f(fmaf(sL, ks[n + 0], -rmL));
            p1 += ex2f(fmaf(sL, ks[n + 1], -rmL));
            p2 += ex2f(fmaf(sL, ks[n + 2], -rmL));
            p3 += ex2f(fmaf(sL, ks[n + 3], -rmL));
        }
        float Z = (p0 + p1) + (p2 + p3);
        sLs[t]  = sL;
        offs[t] = -rmL - lg2f(Z);
    }
    __syncthreads();

    int mbase = w * 32;
    float sl[4], of[4];
    #pragma unroll
    for (int nt = 0; nt < 4; nt++) {
        int mm = mbase + nt * 8 + g;
        sl[nt] = sLs[mm];
        of[nt] = offs[mm];
    }

    float acc[4][4][4];
    #pragma unroll
    for (int ct = 0; ct < 4; ct++)
        #pragma unroll
        for (int nt = 0; nt < 4; nt++)
            #pragma unroll
            for (int u = 0; u < 4; u++) acc[ct][nt][u] = 0.f;

    for (int ch = 0; ch < 16; ch++) {
        int nn0 = ch * 64;
        __syncthreads();
        #pragma unroll
        for (int s = 0; s < 16; s++)
            pvs[(pv_c + s * 4) * 68 + pv_pp] = tf32r(pvf[s]);
        if (ch < 15) {
            int nb2 = nn0 + 64;
            #pragma unroll
            for (int s = 0; s < 16; s++)
                pvf[s] = g_pv[((size_t)b * 64 + (pv_c + s * 4)) * NPOS + nb2 + pv_nn];
        }
        __syncthreads();

        #pragma unroll
        for (int ks8 = 0; ks8 < 8; ks8++) {
            int kk = ks8 * 8 + tg;
            float k0v = ks[nn0 + kk];
            float k4v = ks[nn0 + kk + 4];

            uint2 alo[4], ahi[4];
            #pragma unroll
            for (int ct = 0; ct < 4; ct++) {
                const uint32_t* ap = &pvs[(ct * 16 + g) * 68 + ks8 * 8 + 2 * tg];
                alo[ct] = *reinterpret_cast<const uint2*>(ap);           // (kk, kk+4)
                ahi[ct] = *reinterpret_cast<const uint2*>(ap + 8 * 68);  // row+8
            }

            #pragma unroll
            for (int nt = 0; nt < 4; nt++) {
                float e0 = ex2f(fmaf(sl[nt], k0v, of[nt]));
                float e4 = ex2f(fmaf(sl[nt], k4v, of[nt]));
                int ml = mbase + nt * 8 + g;
                es[ml * 68 + kk]     = e0;
                es[ml * 68 + kk + 4] = e4;
                uint32_t b0 = tf32r(e0);
                uint32_t b1 = tf32r(e4);
                #pragma unroll
                for (int ct = 0; ct < 4; ct++)
                    mma_tf32(acc[ct][nt][0], acc[ct][nt][1], acc[ct][nt][2], acc[ct][nt][3],
                             alo[ct].x, ahi[ct].x, alo[ct].y, ahi[ct].y,
                             b0, b1);
            }
        }

        if (has_attn) {
            __syncwarp();
            float* dst = attn_out + ((size_t)(b * 1024 + m0 + mbase)) * 1024 + nn0 + 2 * l;
            #pragma unroll 8
            for (int r2 = 0; r2 < 32; r2++) {
                float2 val = *reinterpret_cast<const float2*>(&es[(mbase + r2) * 68 + 2 * l]);
                *reinterpret_cast<float2*>(dst + (size_t)r2 * 1024) = val;
            }
        }
    }

    // ---- Epilogue 1: out D-frags -> smem (tf32 bits), layout outS[m][c] ----
    __syncwarp();
    #pragma unroll
    for (int ct = 0; ct < 4; ct++) {
        #pragma unroll
        for (int nt = 0; nt < 4; nt++) {
            int ml = mbase + nt * 8 + 2 * tg;
            int c  = ct * 16 + g;
            outS[ml * 68 + c]           = tf32r(acc[ct][nt][0]);
            outS[(ml + 1) * 68 + c]     = tf32r(acc[ct][nt][1]);
            outS[ml * 68 + c + 8]       = tf32r(acc[ct][nt][2]);
            outS[(ml + 1) * 68 + c + 8] = tf32r(acc[ct][nt][3]);
        }
    }
    __syncthreads();

    // ---- Epilogue 2: up-GEMM ----
    #pragma unroll
    for (int dtl = 0; dtl < 2; dtl++) {
        int dt = w * 2 + dtl;
        uint32_t af[8][4];
        #pragma unroll
        for (int k8 = 0; k8 < 8; k8++) {
            const uint32_t* ap = &g_wuT[(dt * 16 + g) * 64 + k8 * 8 + tg];
            af[k8][0] = ap[0];
            af[k8][1] = ap[8 * 64];
            af[k8][2] = ap[4];
            af[k8][3] = ap[8 * 64 + 4];
        }
        int dab0 = dt * 16 + g;
        int dab1 = dab0 + 8;
        int dd0 = dab0 >> 2, aa0 = (dab0 >> 1) & 1, bb0 = dab0 & 1;
        int dd1 = dab1 >> 2, aa1 = (dab1 >> 1) & 1, bb1 = dab1 & 1;
        float bud0 = __ldg(&bu[dd0]);
        float bud1 = __ldg(&bu[dd1]);

        for (int mt2 = 0; mt2 < 32; mt2++) {
            float e0 = 0.f, e1 = 0.f, e2 = 0.f, e3 = 0.f;
            #pragma unroll
            for (int k8 = 0; k8 < 8; k8++) {
                const uint32_t* bp = &outS[(mt2 * 8 + g) * 68 + k8 * 8 + tg];
                mma_tf32(e0, e1, e2, e3,
                         af[k8][0], af[k8][1], af[k8][2], af[k8][3],
                         bp[0], bp[4]);
            }
            int mg = m0 + mt2 * 8 + 2 * tg;
            int i = mg >> 5, j = mg & 31;
            size_t a0 = (((size_t)(b * 64 + dd0)) * 64 + 2 * i + aa0) * 64 + 2 * j + bb0;
            size_t a1 = (((size_t)(b * 64 + dd1)) * 64 + 2 * i + aa1) * 64 + 2 * j + bb1;
            up[a0]     = e0 + bud0;
            up[a0 + 2] = e1 + bud0;
            up[a1]     = e2 + bud1;
            up[a1 + 2] = e3 + bud1;
        }
    }
}

// ---------------------------------------------------------------------------
extern "C" void kernel_launch(void* const* d_in, const int* in_sizes, int n_in,
                              void* d_out, int out_size) {
    const float* x     = (const float*)d_in[0];
    const float* v     = (const float*)d_in[1];
    const float* wq    = (const float*)d_in[2];
    const float* bq    = (const float*)d_in[3];
    const float* wk    = (const float*)d_in[4];
    const float* bk    = (const float*)d_in[5];
    const float* wv    = (const float*)d_in[6];
    const float* bv    = (const float*)d_in[7];
    const float* wu    = (const float*)d_in[8];
    const float* bu    = (const float*)d_in[9];
    const float* wproj = (const float*)d_in[10];
    const float* bproj = (const float*)d_in[11];

    float* up_out   = (float*)d_out;
    int has_attn    = (out_size > UP_ELEMS) ? 1 : 0;
    float* attn_out = up_out + UP_ELEMS;

    cudaFuncSetAttribute(kproj_part_kernel, cudaFuncAttributeMaxDynamicSharedMemorySize, 65024);
    cudaFuncSetAttribute(conv_x_kernel,     cudaFuncAttributeMaxDynamicSharedMemorySize, 48384);
    cudaFuncSetAttribute(attn_kernel,       cudaFuncAttributeMaxDynamicSharedMemorySize, 93184);

    static cudaStream_t s1 = []() {
        cudaStream_t s;
        cudaStreamCreateWithFlags(&s, cudaStreamNonBlocking);
        return s;
    }();
    static cudaEvent_t evFork = []() {
        cudaEvent_t e;
        cudaEventCreateWithFlags(&e, cudaEventDisableTiming);
        return e;
    }();
    static cudaEvent_t evJoin = []() {
        cudaEvent_t e;
        cudaEventCreateWithFlags(&e, cudaEventDisableTiming);
        return e;
    }();

    cudaEventRecord(evFork, 0);
    cudaStreamWaitEvent(s1, evFork, 0);

    // Branch A (side stream): conv_x
    conv_x_kernel<<<dim3(4, 64), 256, 48384, s1>>>(x, wq, bq, wv, bv);

    // Branch B (main stream): conv_v -> kproj -> kreduce
    conv_v_kernel<<<dim3(42, 64), 256>>>(v, wk, bk, wu);
    kproj_part_kernel<<<dim3(16, 9), 256, 65024>>>(wproj);
    kreduce_kernel<<<dim3(4, 64), 256>>>(bproj);

    cudaEventRecord(evJoin, s1);
    cudaStreamWaitEvent(0, evJoin, 0);

    attn_kernel<<<dim3(4, 64), 256, 93184>>>(attn_out, has_attn, bu, up_out);
}

// round 14
// speedup vs baseline: 1.0495x; 1.0495x over previous
#include <cuda_runtime.h>
#include <cuda_bf16.h>
#include <cstdint>

// Problem constants
#define BATCH 64
#define CH    64
#define HH    64
#define WW    64
#define NPOS  1024        // 32*32
#define KPIN  1134        // 42*27 = 9*126
#define KPOUT 1024
#define UP_ELEMS (BATCH*CH*HH*WW)          // 16777216
#define ATTN_ELEMS (BATCH*NPOS*NPOS)       // 67108864

// Scratch (device globals; no allocation)
__device__ float    g_pv[BATCH * CH * NPOS];   // [b][c][n]
__device__ float    g_q[BATCH * NPOS];
__device__ float    g_k[BATCH * NPOS];
__device__ float    g_kc[BATCH * KPIN];
__device__ float    g_kpart[9 * BATCH * NPOS]; // split-K partials [ks][b][m]
__device__ float    g_kmax[BATCH];
__device__ float    g_kmin[BATCH];
__device__ uint32_t g_wuT[256 * 64];           // tf32 bits, [dab][c]

typedef unsigned long long ull;

__device__ __forceinline__ float ex2f(float x) {
    float y;
    asm("ex2.approx.ftz.f32 %0, %1;" : "=f"(y) : "f"(x));
    return y;
}
__device__ __forceinline__ float lg2f(float x) {
    float y;
    asm("lg2.approx.ftz.f32 %0, %1;" : "=f"(y) : "f"(x));
    return y;
}
__device__ __forceinline__ uint32_t tf32r(float x) {
    uint32_t r;
    asm("cvt.rna.tf32.f32 %0, %1;" : "=r"(r) : "f"(x));
    return r;
}
__device__ __forceinline__ void mma_tf32(float& d0, float& d1, float& d2, float& d3,
                                         uint32_t a0, uint32_t a1, uint32_t a2, uint32_t a3,
                                         uint32_t b0, uint32_t b1) {
    asm("mma.sync.aligned.m16n8k8.row.col.f32.tf32.tf32.f32 "
        "{%0,%1,%2,%3}, {%4,%5,%6,%7}, {%8,%9}, {%0,%1,%2,%3};"
        : "+f"(d0), "+f"(d1), "+f"(d2), "+f"(d3)
        : "r"(a0), "r"(a1), "r"(a2), "r"(a3), "r"(b0), "r"(b1));
}
__device__ __forceinline__ void atomicMaxF(float* addr, float val) {
    if (val >= 0.f) atomicMax(reinterpret_cast<int*>(addr), __float_as_int(val));
    else atomicMin(reinterpret_cast<unsigned int*>(addr),
                   static_cast<unsigned int>(__float_as_int(val)));
}
__device__ __forceinline__ void atomicMinF(float* addr, float val) {
    if (val >= 0.f) atomicMin(reinterpret_cast<int*>(addr), __float_as_int(val));
    else atomicMax(reinterpret_cast<unsigned int*>(addr),
                   static_cast<unsigned int>(__float_as_int(val)));
}

// ---------------------------------------------------------------------------
// Kernel 1: conv2x2(v, wk) -> g_kc[b][ii*27+jj]
// Blocks with ii==0 also stage g_wuT; (ii==0,b==0) inits kmax/kmin.
// ---------------------------------------------------------------------------
__global__ __launch_bounds__(256) void conv_v_kernel(const float* __restrict__ v,
                                                     const float* __restrict__ wk,
                                                     const float* __restrict__ bk,
                                                     const float* __restrict__ wu) {
    __shared__ float vs[64 * 2 * 54];
    __shared__ float wks[256];
    __shared__ float part[8][28];
    int ii = blockIdx.x;
    int b  = blockIdx.y;
    int t  = threadIdx.x;

    if (ii == 0) {
        int idx = b * 256 + t;          // 0..16383, each exactly once
        int dab = idx & 255;
        int c   = idx >> 8;
        g_wuT[dab * 64 + c] = tf32r(wu[c * 256 + dab]);
        if (b == 0 && t < 64) {
            g_kmax[t] = __int_as_float(0xFF800000);   // -inf
            g_kmin[t] = __int_as_float(0x7F800000);   // +inf
        }
    }

    wks[t] = wk[t];
    for (int idx = t; idx < 64 * 2 * 54; idx += 256) {
        int c   = idx / 108;
        int rem = idx - c * 108;
        int a   = rem / 54;
        int col = rem - a * 54;
        vs[idx] = v[((b * 64 + c) * 84 + (2 * ii + a)) * 54 + col];
    }
    __syncthreads();

    if (t < 216) {
        int jj = t % 27;
        int cg = t / 27;
        float acc = 0.f;
        #pragma unroll
        for (int cc = 0; cc < 8; cc++) {
            int c = cg * 8 + cc;
            #pragma unroll
            for (int a = 0; a < 2; a++) {
                float x0 = vs[(c * 2 + a) * 54 + 2 * jj + 0];
                float x1 = vs[(c * 2 + a) * 54 + 2 * jj + 1];
                acc += x0 * wks[c * 4 + a * 2 + 0] + x1 * wks[c * 4 + a * 2 + 1];
            }
        }
        part[cg][jj] = acc;
    }
    __syncthreads();
    if (t < 27) {
        float s = bk[0];
        #pragma unroll
        for (int cg = 0; cg < 8; cg++) s += part[cg][t];
        g_kc[b * KPIN + ii * 27 + t] = s;
    }
}

// ---------------------------------------------------------------------------
// Kernel 2a: split-K partial GEMM.
// grid (16 m-tiles, 9 k-splits), 256 threads, dyn smem = 65024 B.
// ---------------------------------------------------------------------------
__global__ __launch_bounds__(256) void kproj_part_kernel(const float* __restrict__ wproj) {
    extern __shared__ float sm2[];
    float* kcs = sm2;               // [64][127]
    float* ws  = sm2 + 64 * 127;    // [64][127]
    int mt  = blockIdx.x;
    int ksp = blockIdx.y;
    int m0  = mt * 64;
    int k0  = ksp * 126;
    int t   = threadIdx.x;

    for (int idx = t; idx < 64 * 126; idx += 256) {
        int row = idx / 126;
        int jj  = idx - row * 126;
        kcs[row * 127 + jj] = g_kc[row * KPIN + k0 + jj];
        ws[row * 127 + jj]  = wproj[(size_t)(m0 + row) * KPIN + k0 + jj];
    }
    __syncthreads();

    int r  = t >> 4;
    int cc = t & 15;
    int b0 = r * 4;
    int mm0 = cc * 4;

    float acc[4][4];
    #pragma unroll
    for (int i = 0; i < 4; i++)
        #pragma unroll
        for (int j = 0; j < 4; j++) acc[i][j] = 0.f;

    #pragma unroll 3
    for (int jj = 0; jj < 126; jj++) {
        float kv[4], wv_[4];
        #pragma unroll
        for (int v_ = 0; v_ < 4; v_++) kv[v_] = kcs[(b0 + v_) * 127 + jj];
        #pragma unroll
        for (int u = 0; u < 4; u++) wv_[u] = ws[(mm0 + u) * 127 + jj];
        #pragma unroll
        for (int v_ = 0; v_ < 4; v_++)
            #pragma unroll
            for (int u = 0; u < 4; u++) acc[v_][u] += kv[v_] * wv_[u];
    }

    #pragma unroll
    for (int v_ = 0; v_ < 4; v_++)
        #pragma unroll
        for (int u = 0; u < 4; u++)
            g_kpart[((size_t)ksp * 64 + b0 + v_) * NPOS + m0 + mm0 + u] = acc[v_][u];
}

// ---------------------------------------------------------------------------
// Kernel 2b: reduce partials + bias -> g_k; per-b max/min via deterministic
// (order-independent) float-as-int atomics. grid (4, 64), 256 threads.
// ---------------------------------------------------------------------------
__global__ __launch_bounds__(256) void kreduce_kernel(const float* __restrict__ bproj) {
    __shared__ float smax[8], smin[8];
    int b = blockIdx.y, t = threadIdx.x;
    int m = blockIdx.x * 256 + t;
    float s = bproj[m];
    #pragma unroll
    for (int ksp = 0; ksp < 9; ksp++)
        s += g_kpart[((size_t)ksp * 64 + b) * NPOS + m];
    g_k[b * NPOS + m] = s;

    float mx = s, mn = s;
    #pragma unroll
    for (int d = 16; d > 0; d >>= 1) {
        mx = fmaxf(mx, __shfl_xor_sync(0xFFFFFFFF, mx, d));
        mn = fminf(mn, __shfl_xor_sync(0xFFFFFFFF, mn, d));
    }
    if ((t & 31) == 0) { smax[t >> 5] = mx; smin[t >> 5] = mn; }
    __syncthreads();
    if (t < 8) {
        mx = smax[t]; mn = smin[t];
        #pragma unroll
        for (int d = 4; d > 0; d >>= 1) {
            mx = fmaxf(mx, __shfl_xor_sync(0xFF, mx, d));
            mn = fminf(mn, __shfl_xor_sync(0xFF, mn, d));
        }
        if (t == 0) {
            atomicMaxF(&g_kmax[b], mx);
            atomicMinF(&g_kmin[b], mn);
        }
    }
}

// ---------------------------------------------------------------------------
// Kernel 4: conv2x2 of x as tf32 MMA GEMM (im2col at staging).
// grid (4 ntile, 64 b), 256 threads. dyn smem = 48384 B. (R12 config)
// ---------------------------------------------------------------------------
__global__ __launch_bounds__(256, 2) void conv_x_kernel(const float* __restrict__ x,
                                                        const float* __restrict__ wq,
                                                        const float* __restrict__ bq,
                                                        const float* __restrict__ wv,
                                                        const float* __restrict__ bv) {
    extern __shared__ uint32_t cxs[];
    uint32_t* Pn  = cxs;                 // 256*38
    uint32_t* wvs = Pn + 9728;           // 64*36
    float*    wqc = reinterpret_cast<float*>(wvs + 2304);   // 32

    int ntile = blockIdx.x;
    int b     = blockIdx.y;
    int t     = threadIdx.x;
    int w     = t >> 5;
    int l     = t & 31;
    int g     = l >> 2;
    int tg    = l & 3;
    int mt    = w & 3;
    int half  = w >> 2;

    float acc[16][4];
    #pragma unroll
    for (int nt = 0; nt < 16; nt++)
        #pragma unroll
        for (int u = 0; u < 4; u++) acc[nt][u] = 0.f;
    float qacc = 0.f;

    for (int chunk = 0; chunk < 8; chunk++) {
        int k0  = chunk * 32;
        int ci0 = chunk * 8;
        __syncthreads();
        #pragma unroll
        for (int s = 0; s < 8; s++) {
            int idx = t + s * 256;
            int co = idx >> 5, kl = idx & 31;
            wvs[co * 36 + kl] = tf32r(wv[co * 256 + k0 + kl]);
        }
        if (t < 32) wqc[t] = wq[k0 + t];
        #pragma unroll
        for (int s = 0; s < 8; s++) {
            int idx = t + s * 256;
            int cl  = idx >> 8;
            int rem = idx & 255;
            int r   = rem >> 4;
            int c4  = rem & 15;
            float4 xv = *reinterpret_cast<const float4*>(
                &x[(((size_t)b * 64 + ci0 + cl) * 64 + ntile * 16 + r) * 64 + c4 * 4]);
            int n2 = (r >> 1) * 32 + c4 * 2;
            int kb = cl * 4 + (r & 1) * 2;
            uint2 p0 = make_uint2(tf32r(xv.x), tf32r(xv.y));
            uint2 p1 = make_uint2(tf32r(xv.z), tf32r(xv.w));
            *reinterpret_cast<uint2*>(&Pn[n2 * 38 + kb])       = p0;
            *reinterpret_cast<uint2*>(&Pn[(n2 + 1) * 38 + kb]) = p1;
        }
        __syncthreads();

        {
            const uint32_t* pr = &Pn[t * 38];
            #pragma unroll 8
            for (int k = 0; k < 32; k++)
                qacc = fmaf(wqc[k], __uint_as_float(pr[k]), qacc);
        }

        #pragma unroll
        for (int k8 = 0; k8 < 4; k8++) {
            int kk = k8 * 8 + tg;
            const uint32_t* ap = &wvs[(mt * 16 + g) * 36 + kk];
            uint32_t a0 = ap[0];
            uint32_t a1 = ap[8 * 36];
            uint32_t a2 = ap[4];
            uint32_t a3 = ap[8 * 36 + 4];
            #pragma unroll
            for (int nt = 0; nt < 16; nt++) {
                const uint32_t* bp = &Pn[(half * 128 + nt * 8 + g) * 38 + kk];
                mma_tf32(acc[nt][0], acc[nt][1], acc[nt][2], acc[nt][3],
                         a0, a1, a2, a3, bp[0], bp[4]);
            }
        }
    }

    int c0 = mt * 16 + g;
    float bv0 = bv[c0];
    float bv8 = bv[c0 + 8];
    int nb = ntile * 256 + half * 128;
    #pragma unroll
    for (int nt = 0; nt < 16; nt++) {
        int n = nb + nt * 8 + 2 * tg;
        *reinterpret_cast<float2*>(&g_pv[((size_t)b * 64 + c0) * NPOS + n]) =
            make_float2(acc[nt][0] + bv0, acc[nt][1] + bv0);
        *reinterpret_cast<float2*>(&g_pv[((size_t)b * 64 + c0 + 8) * NPOS + n]) =
            make_float2(acc[nt][2] + bv8, acc[nt][3] + bv8);
    }
    g_q[b * NPOS + ntile * 256 + t] = qacc + bq[0];
}

// ---------------------------------------------------------------------------
// Kernel 5: fused softmax + attn write + tf32 MMA GEMM + ConvTranspose2d.
// 256 m-rows/block, grid (4, 64), 256 threads, dyn smem = 93184 B.
// (R12 config; copy-out widened to float4)
// ---------------------------------------------------------------------------
__global__ __launch_bounds__(256, 2) void attn_kernel(float* __restrict__ attn_out,
                                                      int has_attn,
                                                      const float* __restrict__ bu,
                                                      float* __restrict__ up) {
    extern __shared__ float dsm[];
    float*    ks   = dsm;                                      // [1024]
    float*    sLs  = dsm + 1024;                               // [256]
    float*    offs = dsm + 1280;                               // [256]
    uint32_t* pvs  = reinterpret_cast<uint32_t*>(dsm + 1536);  // [64*68]
    float*    es   = dsm + 1536 + 4352;                        // [256*68]
    uint32_t* outS = reinterpret_cast<uint32_t*>(es);          // alias

    const float L2E = 1.4426950408889634f;
    int mt = blockIdx.x;
    int b  = blockIdx.y;
    int m0 = mt * 256;
    int t  = threadIdx.x;
    int w  = t >> 5;
    int l  = t & 31;
    int g  = l >> 2;
    int tg = l & 3;

    for (int n = t; n < NPOS; n += 256) ks[n] = g_k[b * NPOS + n];

    int pv_c  = t >> 6;
    int pv_nn = t & 63;
    float pvf[16];
    #pragma unroll
    for (int s = 0; s < 16; s++)
        pvf[s] = g_pv[((size_t)b * 64 + (pv_c + s * 4)) * NPOS + pv_nn];

    __syncthreads();

    {
        float s   = g_q[b * NPOS + m0 + t] * 0.03125f;   // 1/sqrt(1024)
        float rm  = (s >= 0.f) ? s * g_kmax[b] : s * g_kmin[b];
        float sL  = s * L2E;
        float rmL = rm * L2E;
        float p0 = 0.f, p1 = 0.f, p2 = 0.f, p3 = 0.f;
        #pragma unroll 4
        for (int n = 0; n < 1024; n += 4) {
            p0 += ex2f(fmaf(sL, ks[n + 0], -rmL));
            p1 += ex2f(fmaf(sL, ks[n + 1], -rmL));
            p2 += ex2f(fmaf(sL, ks[n + 2], -rmL));
            p3 += ex2f(fmaf(sL, ks[n + 3], -rmL));
        }
        float Z = (p0 + p1) + (p2 + p3);
        sLs[t]  = sL;
        offs[t] = -rmL - lg2f(Z);
    }
    __syncthreads();

    int mbase = w * 32;
    float sl[4], of[4];
    #pragma unroll
    for (int nt = 0; nt < 4; nt++) {
        int mm = mbase + nt * 8 + g;
        sl[nt] = sLs[mm];
        of[nt] = offs[mm];
    }

    float acc[4][4][4];
    #pragma unroll
    for (int ct = 0; ct < 4; ct++)
        #pragma unroll
        for (int nt = 0; nt < 4; nt++)
            #pragma unroll
            for (int u = 0; u < 4; u++) acc[ct][nt][u] = 0.f;

    for (int ch = 0; ch < 16; ch++) {
        int nn0 = ch * 64;
        __syncthreads();
        #pragma unroll
        for (int s = 0; s < 16; s++)
            pvs[(pv_c + s * 4) * 68 + pv_nn] = tf32r(pvf[s]);
        if (ch < 15) {
            int nb2 = nn0 + 64;
            #pragma unroll
            for (int s = 0; s < 16; s++)
                pvf[s] = g_pv[((size_t)b * 64 + (pv_c + s * 4)) * NPOS + nb2 + pv_nn];
        }
        __syncthreads();

        #pragma unroll
        for (int ks8 = 0; ks8 < 8; ks8++) {
            int kk = ks8 * 8 + tg;
            float k0v = ks[nn0 + kk];
            float k4v = ks[nn0 + kk + 4];

            uint32_t afr[4][4];
            #pragma unroll
            for (int ct = 0; ct < 4; ct++) {
                const uint32_t* ap = &pvs[(ct * 16 + g) * 68 + kk];
                afr[ct][0] = ap[0];
                afr[ct][1] = ap[8 * 68];
                afr[ct][2] = ap[4];
                afr[ct][3] = ap[8 * 68 + 4];
            }

            #pragma unroll
            for (int nt = 0; nt < 4; nt++) {
                float e0 = ex2f(fmaf(sl[nt], k0v, of[nt]));
                float e4 = ex2f(fmaf(sl[nt], k4v, of[nt]));
                int ml = mbase + nt * 8 + g;
                es[ml * 68 + kk]     = e0;
                es[ml * 68 + kk + 4] = e4;
                uint32_t b0 = tf32r(e0);
                uint32_t b1 = tf32r(e4);
                #pragma unroll
                for (int ct = 0; ct < 4; ct++)
                    mma_tf32(acc[ct][nt][0], acc[ct][nt][1], acc[ct][nt][2], acc[ct][nt][3],
                             afr[ct][0], afr[ct][1], afr[ct][2], afr[ct][3],
                             b0, b1);
            }
        }

        // warp-private copy-out, float4: lane covers (row = 2r2+(l>>4), col 4*(l&15))
        if (has_attn) {
            __syncwarp();
            int lr = l >> 4;          // 0..1
            int lc = (l & 15) * 4;    // 0..60
            float* dst = attn_out + ((size_t)(b * 1024 + m0 + mbase + lr)) * 1024 + nn0 + lc;
            #pragma unroll 8
            for (int r2 = 0; r2 < 16; r2++) {
                float4 val = *reinterpret_cast<const float4*>(
                    &es[(mbase + 2 * r2 + lr) * 68 + lc]);
                *reinterpret_cast<float4*>(dst + (size_t)(2 * r2) * 1024) = val;
            }
        }
    }

    // ---- Epilogue 1: out D-frags -> smem (tf32 bits), layout outS[m][c] ----
    __syncwarp();
    #pragma unroll
    for (int ct = 0; ct < 4; ct++) {
        #pragma unroll
        for (int nt = 0; nt < 4; nt++) {
            int ml = mbase + nt * 8 + 2 * tg;
            int c  = ct * 16 + g;
            outS[ml * 68 + c]           = tf32r(acc[ct][nt][0]);
            outS[(ml + 1) * 68 + c]     = tf32r(acc[ct][nt][1]);
            outS[ml * 68 + c + 8]       = tf32r(acc[ct][nt][2]);
            outS[(ml + 1) * 68 + c + 8] = tf32r(acc[ct][nt][3]);
        }
    }
    __syncthreads();

    // ---- Epilogue 2: up-GEMM ----
    #pragma unroll
    for (int dtl = 0; dtl < 2; dtl++) {
        int dt = w * 2 + dtl;
        uint32_t af[8][4];
        #pragma unroll
        for (int k8 = 0; k8 < 8; k8++) {
            const uint32_t* ap = &g_wuT[(dt * 16 + g) * 64 + k8 * 8 + tg];
            af[k8][0] = ap[0];
            af[k8][1] = ap[8 * 64];
            af[k8][2] = ap[4];
            af[k8][3] = ap[8 * 64 + 4];
        }
        int dab0 = dt * 16 + g;
        int dab1 = dab0 + 8;
        int dd0 = dab0 >> 2, aa0 = (dab0 >> 1) & 1, bb0 = dab0 & 1;
        int dd1 = dab1 >> 2, aa1 = (dab1 >> 1) & 1, bb1 = dab1 & 1;
        float bud0 = __ldg(&bu[dd0]);
        float bud1 = __ldg(&bu[dd1]);

        for (int mt2 = 0; mt2 < 32; mt2++) {
            float e0 = 0.f, e1 = 0.f, e2 = 0.f, e3 = 0.f;
            #pragma unroll
            for (int k8 = 0; k8 < 8; k8++) {
                const uint32_t* bp = &outS[(mt2 * 8 + g) * 68 + k8 * 8 + tg];
                mma_tf32(e0, e1, e2, e3,
                         af[k8][0], af[k8][1], af[k8][2], af[k8][3],
                         bp[0], bp[4]);
            }
            int mg = m0 + mt2 * 8 + 2 * tg;
            int i = mg >> 5, j = mg & 31;
            size_t a0 = (((size_t)(b * 64 + dd0)) * 64 + 2 * i + aa0) * 64 + 2 * j + bb0;
            size_t a1 = (((size_t)(b * 64 + dd1)) * 64 + 2 * i + aa1) * 64 + 2 * j + bb1;
            up[a0]     = e0 + bud0;
            up[a0 + 2] = e1 + bud0;
            up[a1]     = e2 + bud1;
            up[a1 + 2] = e3 + bud1;
        }
    }
}

// ---------------------------------------------------------------------------
extern "C" void kernel_launch(void* const* d_in, const int* in_sizes, int n_in,
                              void* d_out, int out_size) {
    const float* x     = (const float*)d_in[0];
    const float* v     = (const float*)d_in[1];
    const float* wq    = (const float*)d_in[2];
    const float* bq    = (const float*)d_in[3];
    const float* wk    = (const float*)d_in[4];
    const float* bk    = (const float*)d_in[5];
    const float* wv    = (const float*)d_in[6];
    const float* bv    = (const float*)d_in[7];
    const float* wu    = (const float*)d_in[8];
    const float* bu    = (const float*)d_in[9];
    const float* wproj = (const float*)d_in[10];
    const float* bproj = (const float*)d_in[11];

    float* up_out   = (float*)d_out;
    int has_attn    = (out_size > UP_ELEMS) ? 1 : 0;
    float* attn_out = up_out + UP_ELEMS;

    cudaFuncSetAttribute(kproj_part_kernel, cudaFuncAttributeMaxDynamicSharedMemorySize, 65024);
    cudaFuncSetAttribute(conv_x_kernel,     cudaFuncAttributeMaxDynamicSharedMemorySize, 48384);
    cudaFuncSetAttribute(attn_kernel,       cudaFuncAttributeMaxDynamicSharedMemorySize, 93184);

    static cudaStream_t s1 = []() {
        cudaStream_t s;
        cudaStreamCreateWithFlags(&s, cudaStreamNonBlocking);
        return s;
    }();
    static cudaEvent_t evFork = []() {
        cudaEvent_t e;
        cudaEventCreateWithFlags(&e, cudaEventDisableTiming);
        return e;
    }();
    static cudaEvent_t evJoin = []() {
        cudaEvent_t e;
        cudaEventCreateWithFlags(&e, cudaEventDisableTiming);
        return e;
    }();

    cudaEventRecord(evFork, 0);
    cudaStreamWaitEvent(s1, evFork, 0);

    // Branch A (side stream): conv_x
    conv_x_kernel<<<dim3(4, 64), 256, 48384, s1>>>(x, wq, bq, wv, bv);

    // Branch B (main stream): conv_v -> kproj -> kreduce
    conv_v_kernel<<<dim3(42, 64), 256>>>(v, wk, bk, wu);
    kproj_part_kernel<<<dim3(16, 9), 256, 65024>>>(wproj);
    kreduce_kernel<<<dim3(4, 64), 256>>>(bproj);

    cudaEventRecord(evJoin, s1);
    cudaStreamWaitEvent(0, evJoin, 0);

    attn_kernel<<<dim3(4, 64), 256, 93184>>>(attn_out, has_attn, bu, up_out);
}

// round 15
// speedup vs baseline: 1.0719x; 1.0214x over previous
#include <cuda_runtime.h>
#include <cuda_bf16.h>
#include <cstdint>

// Problem constants
#define BATCH 64
#define CH    64
#define HH    64
#define WW    64
#define NPOS  1024        // 32*32
#define KPIN  1134        // 42*27 = 9*126
#define KPOUT 1024
#define UP_ELEMS (BATCH*CH*HH*WW)          // 16777216
#define ATTN_ELEMS (BATCH*NPOS*NPOS)       // 67108864

// Scratch (device globals; no allocation)
__device__ float    g_pv[BATCH * CH * NPOS];   // [b][c][n]
__device__ float    g_q[BATCH * NPOS];
__device__ float    g_k[BATCH * NPOS];
__device__ float    g_kc[BATCH * KPIN];
__device__ float    g_kpart[9 * BATCH * NPOS]; // split-K partials [ks][b][m]
__device__ float    g_kmax[BATCH];
__device__ float    g_kmin[BATCH];
__device__ uint32_t g_wuT[256 * 64];           // tf32 bits, [dab][c]

typedef unsigned long long ull;

__device__ __forceinline__ float ex2f(float x) {
    float y;
    asm("ex2.approx.ftz.f32 %0, %1;" : "=f"(y) : "f"(x));
    return y;
}
__device__ __forceinline__ float lg2f(float x) {
    float y;
    asm("lg2.approx.ftz.f32 %0, %1;" : "=f"(y) : "f"(x));
    return y;
}
__device__ __forceinline__ uint32_t tf32r(float x) {
    uint32_t r;
    asm("cvt.rna.tf32.f32 %0, %1;" : "=r"(r) : "f"(x));
    return r;
}
__device__ __forceinline__ void mma_tf32(float& d0, float& d1, float& d2, float& d3,
                                         uint32_t a0, uint32_t a1, uint32_t a2, uint32_t a3,
                                         uint32_t b0, uint32_t b1) {
    asm("mma.sync.aligned.m16n8k8.row.col.f32.tf32.tf32.f32 "
        "{%0,%1,%2,%3}, {%4,%5,%6,%7}, {%8,%9}, {%0,%1,%2,%3};"
        : "+f"(d0), "+f"(d1), "+f"(d2), "+f"(d3)
        : "r"(a0), "r"(a1), "r"(a2), "r"(a3), "r"(b0), "r"(b1));
}
__device__ __forceinline__ void atomicMaxF(float* addr, float val) {
    if (val >= 0.f) atomicMax(reinterpret_cast<int*>(addr), __float_as_int(val));
    else atomicMin(reinterpret_cast<unsigned int*>(addr),
                   static_cast<unsigned int>(__float_as_int(val)));
}
__device__ __forceinline__ void atomicMinF(float* addr, float val) {
    if (val >= 0.f) atomicMin(reinterpret_cast<int*>(addr), __float_as_int(val));
    else atomicMax(reinterpret_cast<unsigned int*>(addr),
                   static_cast<unsigned int>(__float_as_int(val)));
}

// ---------------------------------------------------------------------------
// Kernel 1: conv2x2(v, wk) -> g_kc[b][ii*27+jj]
// Blocks with ii==0 also stage g_wuT; (ii==0,b==0) inits kmax/kmin.
// ---------------------------------------------------------------------------
__global__ __launch_bounds__(256) void conv_v_kernel(const float* __restrict__ v,
                                                     const float* __restrict__ wk,
                                                     const float* __restrict__ bk,
                                                     const float* __restrict__ wu) {
    __shared__ float vs[64 * 2 * 54];
    __shared__ float wks[256];
    __shared__ float part[8][28];
    int ii = blockIdx.x;
    int b  = blockIdx.y;
    int t  = threadIdx.x;

    if (ii == 0) {
        int idx = b * 256 + t;          // 0..16383, each exactly once
        int dab = idx & 255;
        int c   = idx >> 8;
        g_wuT[dab * 64 + c] = tf32r(wu[c * 256 + dab]);
        if (b == 0 && t < 64) {
            g_kmax[t] = __int_as_float(0xFF800000);   // -inf
            g_kmin[t] = __int_as_float(0x7F800000);   // +inf
        }
    }

    wks[t] = wk[t];
    for (int idx = t; idx < 64 * 2 * 54; idx += 256) {
        int c   = idx / 108;
        int rem = idx - c * 108;
        int a   = rem / 54;
        int col = rem - a * 54;
        vs[idx] = v[((b * 64 + c) * 84 + (2 * ii + a)) * 54 + col];
    }
    __syncthreads();

    if (t < 216) {
        int jj = t % 27;
        int cg = t / 27;
        float acc = 0.f;
        #pragma unroll
        for (int cc = 0; cc < 8; cc++) {
            int c = cg * 8 + cc;
            #pragma unroll
            for (int a = 0; a < 2; a++) {
                float x0 = vs[(c * 2 + a) * 54 + 2 * jj + 0];
                float x1 = vs[(c * 2 + a) * 54 + 2 * jj + 1];
                acc += x0 * wks[c * 4 + a * 2 + 0] + x1 * wks[c * 4 + a * 2 + 1];
            }
        }
        part[cg][jj] = acc;
    }
    __syncthreads();
    if (t < 27) {
        float s = bk[0];
        #pragma unroll
        for (int cg = 0; cg < 8; cg++) s += part[cg][t];
        g_kc[b * KPIN + ii * 27 + t] = s;
    }
}

// ---------------------------------------------------------------------------
// Kernel 2a: split-K partial GEMM.
// grid (16 m-tiles, 9 k-splits), 256 threads, dyn smem = 65024 B.
// ---------------------------------------------------------------------------
__global__ __launch_bounds__(256) void kproj_part_kernel(const float* __restrict__ wproj) {
    extern __shared__ float sm2[];
    float* kcs = sm2;               // [64][127]
    float* ws  = sm2 + 64 * 127;    // [64][127]
    int mt  = blockIdx.x;
    int ksp = blockIdx.y;
    int m0  = mt * 64;
    int k0  = ksp * 126;
    int t   = threadIdx.x;

    for (int idx = t; idx < 64 * 126; idx += 256) {
        int row = idx / 126;
        int jj  = idx - row * 126;
        kcs[row * 127 + jj] = g_kc[row * KPIN + k0 + jj];
        ws[row * 127 + jj]  = wproj[(size_t)(m0 + row) * KPIN + k0 + jj];
    }
    __syncthreads();

    int r  = t >> 4;
    int cc = t & 15;
    int b0 = r * 4;
    int mm0 = cc * 4;

    float acc[4][4];
    #pragma unroll
    for (int i = 0; i < 4; i++)
        #pragma unroll
        for (int j = 0; j < 4; j++) acc[i][j] = 0.f;

    #pragma unroll 3
    for (int jj = 0; jj < 126; jj++) {
        float kv[4], wv_[4];
        #pragma unroll
        for (int v_ = 0; v_ < 4; v_++) kv[v_] = kcs[(b0 + v_) * 127 + jj];
        #pragma unroll
        for (int u = 0; u < 4; u++) wv_[u] = ws[(mm0 + u) * 127 + jj];
        #pragma unroll
        for (int v_ = 0; v_ < 4; v_++)
            #pragma unroll
            for (int u = 0; u < 4; u++) acc[v_][u] += kv[v_] * wv_[u];
    }

    #pragma unroll
    for (int v_ = 0; v_ < 4; v_++)
        #pragma unroll
        for (int u = 0; u < 4; u++)
            g_kpart[((size_t)ksp * 64 + b0 + v_) * NPOS + m0 + mm0 + u] = acc[v_][u];
}

// ---------------------------------------------------------------------------
// Kernel 2b: reduce partials + bias -> g_k; per-b max/min via deterministic
// (order-independent) float-as-int atomics. grid (4, 64), 256 threads.
// ---------------------------------------------------------------------------
__global__ __launch_bounds__(256) void kreduce_kernel(const float* __restrict__ bproj) {
    __shared__ float smax[8], smin[8];
    int b = blockIdx.y, t = threadIdx.x;
    int m = blockIdx.x * 256 + t;
    float s = bproj[m];
    #pragma unroll
    for (int ksp = 0; ksp < 9; ksp++)
        s += g_kpart[((size_t)ksp * 64 + b) * NPOS + m];
    g_k[b * NPOS + m] = s;

    float mx = s, mn = s;
    #pragma unroll
    for (int d = 16; d > 0; d >>= 1) {
        mx = fmaxf(mx, __shfl_xor_sync(0xFFFFFFFF, mx, d));
        mn = fminf(mn, __shfl_xor_sync(0xFFFFFFFF, mn, d));
    }
    if ((t & 31) == 0) { smax[t >> 5] = mx; smin[t >> 5] = mn; }
    __syncthreads();
    if (t < 8) {
        mx = smax[t]; mn = smin[t];
        #pragma unroll
        for (int d = 4; d > 0; d >>= 1) {
            mx = fmaxf(mx, __shfl_xor_sync(0xFF, mx, d));
            mn = fminf(mn, __shfl_xor_sync(0xFF, mn, d));
        }
        if (t == 0) {
            atomicMaxF(&g_kmax[b], mx);
            atomicMinF(&g_kmin[b], mn);
        }
    }
}

// ---------------------------------------------------------------------------
// Kernel 4: conv2x2 of x as tf32 MMA GEMM (im2col at staging).
// Pn stride widened 38 -> 44 words: rows 16B-aligned so the q-dot uses
// LDS.128 (8/thread/chunk instead of 32 scalar); MMA B-frag banks stay
// conflict-free (12g mod 32 distinct, g=0..7).
// grid (4 ntile, 64 b), 256 threads. dyn smem = 54400 B, 2 blocks/SM.
// ---------------------------------------------------------------------------
__global__ __launch_bounds__(256, 2) void conv_x_kernel(const float* __restrict__ x,
                                                        const float* __restrict__ wq,
                                                        const float* __restrict__ bq,
                                                        const float* __restrict__ wv,
                                                        const float* __restrict__ bv) {
    extern __shared__ uint32_t cxs[];
    uint32_t* Pn  = cxs;                  // 256*44 = 11264 u32
    uint32_t* wvs = Pn + 11264;           // 64*36  = 2304 u32
    float*    wqc = reinterpret_cast<float*>(wvs + 2304);   // 32

    int ntile = blockIdx.x;
    int b     = blockIdx.y;
    int t     = threadIdx.x;
    int w     = t >> 5;
    int l     = t & 31;
    int g     = l >> 2;
    int tg    = l & 3;
    int mt    = w & 3;
    int half  = w >> 2;

    float acc[16][4];
    #pragma unroll
    for (int nt = 0; nt < 16; nt++)
        #pragma unroll
        for (int u = 0; u < 4; u++) acc[nt][u] = 0.f;
    float qacc = 0.f;

    for (int chunk = 0; chunk < 8; chunk++) {
        int k0  = chunk * 32;
        int ci0 = chunk * 8;
        __syncthreads();
        #pragma unroll
        for (int s = 0; s < 8; s++) {
            int idx = t + s * 256;
            int co = idx >> 5, kl = idx & 31;
            wvs[co * 36 + kl] = tf32r(wv[co * 256 + k0 + kl]);
        }
        if (t < 32) wqc[t] = wq[k0 + t];
        #pragma unroll
        for (int s = 0; s < 8; s++) {
            int idx = t + s * 256;
            int cl  = idx >> 8;
            int rem = idx & 255;
            int r   = rem >> 4;
            int c4  = rem & 15;
            float4 xv = *reinterpret_cast<const float4*>(
                &x[(((size_t)b * 64 + ci0 + cl) * 64 + ntile * 16 + r) * 64 + c4 * 4]);
            int n2 = (r >> 1) * 32 + c4 * 2;
            int kb = cl * 4 + (r & 1) * 2;
            uint2 p0 = make_uint2(tf32r(xv.x), tf32r(xv.y));
            uint2 p1 = make_uint2(tf32r(xv.z), tf32r(xv.w));
            *reinterpret_cast<uint2*>(&Pn[n2 * 44 + kb])       = p0;
            *reinterpret_cast<uint2*>(&Pn[(n2 + 1) * 44 + kb]) = p1;
        }
        __syncthreads();

        // q partial: 8x LDS.128 per thread (16B-aligned rows)
        {
            const uint4* pr4 = reinterpret_cast<const uint4*>(&Pn[t * 44]);
            #pragma unroll
            for (int i = 0; i < 8; i++) {
                uint4 pv4 = pr4[i];
                qacc = fmaf(wqc[4 * i + 0], __uint_as_float(pv4.x), qacc);
                qacc = fmaf(wqc[4 * i + 1], __uint_as_float(pv4.y), qacc);
                qacc = fmaf(wqc[4 * i + 2], __uint_as_float(pv4.z), qacc);
                qacc = fmaf(wqc[4 * i + 3], __uint_as_float(pv4.w), qacc);
            }
        }

        #pragma unroll
        for (int k8 = 0; k8 < 4; k8++) {
            int kk = k8 * 8 + tg;
            const uint32_t* ap = &wvs[(mt * 16 + g) * 36 + kk];
            uint32_t a0 = ap[0];
            uint32_t a1 = ap[8 * 36];
            uint32_t a2 = ap[4];
            uint32_t a3 = ap[8 * 36 + 4];
            #pragma unroll
            for (int nt = 0; nt < 16; nt++) {
                const uint32_t* bp = &Pn[(half * 128 + nt * 8 + g) * 44 + kk];
                mma_tf32(acc[nt][0], acc[nt][1], acc[nt][2], acc[nt][3],
                         a0, a1, a2, a3, bp[0], bp[4]);
            }
        }
    }

    int c0 = mt * 16 + g;
    float bv0 = bv[c0];
    float bv8 = bv[c0 + 8];
    int nb = ntile * 256 + half * 128;
    #pragma unroll
    for (int nt = 0; nt < 16; nt++) {
        int n = nb + nt * 8 + 2 * tg;
        *reinterpret_cast<float2*>(&g_pv[((size_t)b * 64 + c0) * NPOS + n]) =
            make_float2(acc[nt][0] + bv0, acc[nt][1] + bv0);
        *reinterpret_cast<float2*>(&g_pv[((size_t)b * 64 + c0 + 8) * NPOS + n]) =
            make_float2(acc[nt][2] + bv8, acc[nt][3] + bv8);
    }
    g_q[b * NPOS + ntile * 256 + t] = qacc + bq[0];
}

// ---------------------------------------------------------------------------
// Kernel 5: fused softmax + attn write + tf32 MMA GEMM + ConvTranspose2d.
// 256 m-rows/block, grid (4, 64), 256 threads, dyn smem = 93184 B.
// (exact R12 config — measured 121.9us)
// ---------------------------------------------------------------------------
__global__ __launch_bounds__(256, 2) void attn_kernel(float* __restrict__ attn_out,
                                                      int has_attn,
                                                      const float* __restrict__ bu,
                                                      float* __restrict__ up) {
    extern __shared__ float dsm[];
    float*    ks   = dsm;                                      // [1024]
    float*    sLs  = dsm + 1024;                               // [256]
    float*    offs = dsm + 1280;                               // [256]
    uint32_t* pvs  = reinterpret_cast<uint32_t*>(dsm + 1536);  // [64*68]
    float*    es   = dsm + 1536 + 4352;                        // [256*68]
    uint32_t* outS = reinterpret_cast<uint32_t*>(es);          // alias

    const float L2E = 1.4426950408889634f;
    int mt = blockIdx.x;
    int b  = blockIdx.y;
    int m0 = mt * 256;
    int t  = threadIdx.x;
    int w  = t >> 5;
    int l  = t & 31;
    int g  = l >> 2;
    int tg = l & 3;

    for (int n = t; n < NPOS; n += 256) ks[n] = g_k[b * NPOS + n];

    int pv_c  = t >> 6;
    int pv_nn = t & 63;
    float pvf[16];
    #pragma unroll
    for (int s = 0; s < 16; s++)
        pvf[s] = g_pv[((size_t)b * 64 + (pv_c + s * 4)) * NPOS + pv_nn];

    __syncthreads();

    {
        float s   = g_q[b * NPOS + m0 + t] * 0.03125f;   // 1/sqrt(1024)
        float rm  = (s >= 0.f) ? s * g_kmax[b] : s * g_kmin[b];
        float sL  = s * L2E;
        float rmL = rm * L2E;
        float p0 = 0.f, p1 = 0.f, p2 = 0.f, p3 = 0.f;
        #pragma unroll 4
        for (int n = 0; n < 1024; n += 4) {
            p0 += ex2f(fmaf(sL, ks[n + 0], -rmL));
            p1 += ex2f(fmaf(sL, ks[n + 1], -rmL));
            p2 += ex2f(fmaf(sL, ks[n + 2], -rmL));
            p3 += ex2f(fmaf(sL, ks[n + 3], -rmL));
        }
        float Z = (p0 + p1) + (p2 + p3);
        sLs[t]  = sL;
        offs[t] = -rmL - lg2f(Z);
    }
    __syncthreads();

    int mbase = w * 32;
    float sl[4], of[4];
    #pragma unroll
    for (int nt = 0; nt < 4; nt++) {
        int mm = mbase + nt * 8 + g;
        sl[nt] = sLs[mm];
        of[nt] = offs[mm];
    }

    float acc[4][4][4];
    #pragma unroll
    for (int ct = 0; ct < 4; ct++)
        #pragma unroll
        for (int nt = 0; nt < 4; nt++)
            #pragma unroll
            for (int u = 0; u < 4; u++) acc[ct][nt][u] = 0.f;

    for (int ch = 0; ch < 16; ch++) {
        int nn0 = ch * 64;
        __syncthreads();
        #pragma unroll
        for (int s = 0; s < 16; s++)
            pvs[(pv_c + s * 4) * 68 + pv_nn] = tf32r(pvf[s]);
        if (ch < 15) {
            int nb2 = nn0 + 64;
            #pragma unroll
            for (int s = 0; s < 16; s++)
                pvf[s] = g_pv[((size_t)b * 64 + (pv_c + s * 4)) * NPOS + nb2 + pv_nn];
        }
        __syncthreads();

        #pragma unroll
        for (int ks8 = 0; ks8 < 8; ks8++) {
            int kk = ks8 * 8 + tg;
            float k0v = ks[nn0 + kk];
            float k4v = ks[nn0 + kk + 4];

            uint32_t afr[4][4];
            #pragma unroll
            for (int ct = 0; ct < 4; ct++) {
                const uint32_t* ap = &pvs[(ct * 16 + g) * 68 + kk];
                afr[ct][0] = ap[0];
                afr[ct][1] = ap[8 * 68];
                afr[ct][2] = ap[4];
                afr[ct][3] = ap[8 * 68 + 4];
            }

            #pragma unroll
            for (int nt = 0; nt < 4; nt++) {
                float e0 = ex2f(fmaf(sl[nt], k0v, of[nt]));
                float e4 = ex2f(fmaf(sl[nt], k4v, of[nt]));
                int ml = mbase + nt * 8 + g;
                es[ml * 68 + kk]     = e0;
                es[ml * 68 + kk + 4] = e4;
                uint32_t b0 = tf32r(e0);
                uint32_t b1 = tf32r(e4);
                #pragma unroll
                for (int ct = 0; ct < 4; ct++)
                    mma_tf32(acc[ct][nt][0], acc[ct][nt][1], acc[ct][nt][2], acc[ct][nt][3],
                             afr[ct][0], afr[ct][1], afr[ct][2], afr[ct][3],
                             b0, b1);
            }
        }

        // warp-private coalesced attn write: own 32 rows, 256 B each
        if (has_attn) {
            __syncwarp();
            float* dst = attn_out + ((size_t)(b * 1024 + m0 + mbase)) * 1024 + nn0 + 2 * l;
            #pragma unroll 8
            for (int r2 = 0; r2 < 32; r2++) {
                float2 val = *reinterpret_cast<const float2*>(&es[(mbase + r2) * 68 + 2 * l]);
                *reinterpret_cast<float2*>(dst + (size_t)r2 * 1024) = val;
            }
        }
    }

    // ---- Epilogue 1: out D-frags -> smem (tf32 bits), layout outS[m][c] ----
    __syncwarp();
    #pragma unroll
    for (int ct = 0; ct < 4; ct++) {
        #pragma unroll
        for (int nt = 0; nt < 4; nt++) {
            int ml = mbase + nt * 8 + 2 * tg;
            int c  = ct * 16 + g;
            outS[ml * 68 + c]           = tf32r(acc[ct][nt][0]);
            outS[(ml + 1) * 68 + c]     = tf32r(acc[ct][nt][1]);
            outS[ml * 68 + c + 8]       = tf32r(acc[ct][nt][2]);
            outS[(ml + 1) * 68 + c + 8] = tf32r(acc[ct][nt][3]);
        }
    }
    __syncthreads();

    // ---- Epilogue 2: up-GEMM ----
    #pragma unroll
    for (int dtl = 0; dtl < 2; dtl++) {
        int dt = w * 2 + dtl;
        uint32_t af[8][4];
        #pragma unroll
        for (int k8 = 0; k8 < 8; k8++) {
            const uint32_t* ap = &g_wuT[(dt * 16 + g) * 64 + k8 * 8 + tg];
            af[k8][0] = ap[0];
            af[k8][1] = ap[8 * 64];
            af[k8][2] = ap[4];
            af[k8][3] = ap[8 * 64 + 4];
        }
        int dab0 = dt * 16 + g;
        int dab1 = dab0 + 8;
        int dd0 = dab0 >> 2, aa0 = (dab0 >> 1) & 1, bb0 = dab0 & 1;
        int dd1 = dab1 >> 2, aa1 = (dab1 >> 1) & 1, bb1 = dab1 & 1;
        float bud0 = __ldg(&bu[dd0]);
        float bud1 = __ldg(&bu[dd1]);

        for (int mt2 = 0; mt2 < 32; mt2++) {
            float e0 = 0.f, e1 = 0.f, e2 = 0.f, e3 = 0.f;
            #pragma unroll
            for (int k8 = 0; k8 < 8; k8++) {
                const uint32_t* bp = &outS[(mt2 * 8 + g) * 68 + k8 * 8 + tg];
                mma_tf32(e0, e1, e2, e3,
                         af[k8][0], af[k8][1], af[k8][2], af[k8][3],
                         bp[0], bp[4]);
            }
            int mg = m0 + mt2 * 8 + 2 * tg;
            int i = mg >> 5, j = mg & 31;
            size_t a0 = (((size_t)(b * 64 + dd0)) * 64 + 2 * i + aa0) * 64 + 2 * j + bb0;
            size_t a1 = (((size_t)(b * 64 + dd1)) * 64 + 2 * i + aa1) * 64 + 2 * j + bb1;
            up[a0]     = e0 + bud0;
            up[a0 + 2] = e1 + bud0;
            up[a1]     = e2 + bud1;
            up[a1 + 2] = e3 + bud1;
        }
    }
}

// ---------------------------------------------------------------------------
extern "C" void kernel_launch(void* const* d_in, const int* in_sizes, int n_in,
                              void* d_out, int out_size) {
    const float* x     = (const float*)d_in[0];
    const float* v     = (const float*)d_in[1];
    const float* wq    = (const float*)d_in[2];
    const float* bq    = (const float*)d_in[3];
    const float* wk    = (const float*)d_in[4];
    const float* bk    = (const float*)d_in[5];
    const float* wv    = (const float*)d_in[6];
    const float* bv    = (const float*)d_in[7];
    const float* wu    = (const float*)d_in[8];
    const float* bu    = (const float*)d_in[9];
    const float* wproj = (const float*)d_in[10];
    const float* bproj = (const float*)d_in[11];

    float* up_out   = (float*)d_out;
    int has_attn    = (out_size > UP_ELEMS) ? 1 : 0;
    float* attn_out = up_out + UP_ELEMS;

    cudaFuncSetAttribute(kproj_part_kernel, cudaFuncAttributeMaxDynamicSharedMemorySize, 65024);
    cudaFuncSetAttribute(conv_x_kernel,     cudaFuncAttributeMaxDynamicSharedMemorySize, 54400);
    cudaFuncSetAttribute(attn_kernel,       cudaFuncAttributeMaxDynamicSharedMemorySize, 93184);

    static cudaStream_t s1 = []() {
        cudaStream_t s;
        cudaStreamCreateWithFlags(&s, cudaStreamNonBlocking);
        return s;
    }();
    static cudaEvent_t evFork = []() {
        cudaEvent_t e;
        cudaEventCreateWithFlags(&e, cudaEventDisableTiming);
        return e;
    }();
    static cudaEvent_t evJoin = []() {
        cudaEvent_t e;
        cudaEventCreateWithFlags(&e, cudaEventDisableTiming);
        return e;
    }();

    cudaEventRecord(evFork, 0);
    cudaStreamWaitEvent(s1, evFork, 0);

    // Branch A (side stream): conv_x
    conv_x_kernel<<<dim3(4, 64), 256, 54400, s1>>>(x, wq, bq, wv, bv);

    // Branch B (main stream): conv_v -> kproj -> kreduce
    conv_v_kernel<<<dim3(42, 64), 256>>>(v, wk, bk, wu);
    kproj_part_kernel<<<dim3(16, 9), 256, 65024>>>(wproj);
    kreduce_kernel<<<dim3(4, 64), 256>>>(bproj);

    cudaEventRecord(evJoin, s1);
    cudaStreamWaitEvent(0, evJoin, 0);

    attn_kernel<<<dim3(4, 64), 256, 93184>>>(attn_out, has_attn, bu, up_out);
}

// round 16
// speedup vs baseline: 1.0926x; 1.0193x over previous
#include <cuda_runtime.h>
#include <cuda_bf16.h>
#include <cstdint>

// Problem constants
#define BATCH 64
#define CH    64
#define HH    64
#define WW    64
#define NPOS  1024        // 32*32
#define KPIN  1134        // 42*27 = 9*126
#define KPOUT 1024
#define UP_ELEMS (BATCH*CH*HH*WW)          // 16777216
#define ATTN_ELEMS (BATCH*NPOS*NPOS)       // 67108864

// Scratch (device globals; no allocation)
__device__ float    g_pv[BATCH * CH * NPOS];   // [b][c][n]
__device__ float    g_q[BATCH * NPOS];
__device__ float    g_kc[BATCH * KPIN];
__device__ float    g_kpart[9 * BATCH * NPOS]; // split-K partials [ks][b][m]
__device__ uint32_t g_wuT[256 * 64];           // tf32 bits, [dab][c]

typedef unsigned long long ull;

__device__ __forceinline__ float ex2f(float x) {
    float y;
    asm("ex2.approx.ftz.f32 %0, %1;" : "=f"(y) : "f"(x));
    return y;
}
__device__ __forceinline__ float lg2f(float x) {
    float y;
    asm("lg2.approx.ftz.f32 %0, %1;" : "=f"(y) : "f"(x));
    return y;
}
__device__ __forceinline__ uint32_t tf32r(float x) {
    uint32_t r;
    asm("cvt.rna.tf32.f32 %0, %1;" : "=r"(r) : "f"(x));
    return r;
}
__device__ __forceinline__ void mma_tf32(float& d0, float& d1, float& d2, float& d3,
                                         uint32_t a0, uint32_t a1, uint32_t a2, uint32_t a3,
                                         uint32_t b0, uint32_t b1) {
    asm("mma.sync.aligned.m16n8k8.row.col.f32.tf32.tf32.f32 "
        "{%0,%1,%2,%3}, {%4,%5,%6,%7}, {%8,%9}, {%0,%1,%2,%3};"
        : "+f"(d0), "+f"(d1), "+f"(d2), "+f"(d3)
        : "r"(a0), "r"(a1), "r"(a2), "r"(a3), "r"(b0), "r"(b1));
}

// ---------------------------------------------------------------------------
// Kernel 1: conv2x2(v, wk) -> g_kc[b][ii*27+jj]
// Blocks with ii==0 also stage g_wuT (tf32 transpose of wu).
// ---------------------------------------------------------------------------
__global__ __launch_bounds__(256) void conv_v_kernel(const float* __restrict__ v,
                                                     const float* __restrict__ wk,
                                                     const float* __restrict__ bk,
                                                     const float* __restrict__ wu) {
    __shared__ float vs[64 * 2 * 54];
    __shared__ float wks[256];
    __shared__ float part[8][28];
    int ii = blockIdx.x;
    int b  = blockIdx.y;
    int t  = threadIdx.x;

    if (ii == 0) {
        int idx = b * 256 + t;          // 0..16383, each exactly once
        int dab = idx & 255;
        int c   = idx >> 8;
        g_wuT[dab * 64 + c] = tf32r(wu[c * 256 + dab]);
    }

    wks[t] = wk[t];
    for (int idx = t; idx < 64 * 2 * 54; idx += 256) {
        int c   = idx / 108;
        int rem = idx - c * 108;
        int a   = rem / 54;
        int col = rem - a * 54;
        vs[idx] = v[((b * 64 + c) * 84 + (2 * ii + a)) * 54 + col];
    }
    __syncthreads();

    if (t < 216) {
        int jj = t % 27;
        int cg = t / 27;
        float acc = 0.f;
        #pragma unroll
        for (int cc = 0; cc < 8; cc++) {
            int c = cg * 8 + cc;
            #pragma unroll
            for (int a = 0; a < 2; a++) {
                float x0 = vs[(c * 2 + a) * 54 + 2 * jj + 0];
                float x1 = vs[(c * 2 + a) * 54 + 2 * jj + 1];
                acc += x0 * wks[c * 4 + a * 2 + 0] + x1 * wks[c * 4 + a * 2 + 1];
            }
        }
        part[cg][jj] = acc;
    }
    __syncthreads();
    if (t < 27) {
        float s = bk[0];
        #pragma unroll
        for (int cg = 0; cg < 8; cg++) s += part[cg][t];
        g_kc[b * KPIN + ii * 27 + t] = s;
    }
}

// ---------------------------------------------------------------------------
// Kernel 2: split-K partial GEMM.
// grid (16 m-tiles, 9 k-splits), 256 threads, dyn smem = 65024 B.
// ---------------------------------------------------------------------------
__global__ __launch_bounds__(256) void kproj_part_kernel(const float* __restrict__ wproj) {
    extern __shared__ float sm2[];
    float* kcs = sm2;               // [64][127]
    float* ws  = sm2 + 64 * 127;    // [64][127]
    int mt  = blockIdx.x;
    int ksp = blockIdx.y;
    int m0  = mt * 64;
    int k0  = ksp * 126;
    int t   = threadIdx.x;

    for (int idx = t; idx < 64 * 126; idx += 256) {
        int row = idx / 126;
        int jj  = idx - row * 126;
        kcs[row * 127 + jj] = g_kc[row * KPIN + k0 + jj];
        ws[row * 127 + jj]  = wproj[(size_t)(m0 + row) * KPIN + k0 + jj];
    }
    __syncthreads();

    int r  = t >> 4;
    int cc = t & 15;
    int b0 = r * 4;
    int mm0 = cc * 4;

    float acc[4][4];
    #pragma unroll
    for (int i = 0; i < 4; i++)
        #pragma unroll
        for (int j = 0; j < 4; j++) acc[i][j] = 0.f;

    #pragma unroll 3
    for (int jj = 0; jj < 126; jj++) {
        float kv[4], wv_[4];
        #pragma unroll
        for (int v_ = 0; v_ < 4; v_++) kv[v_] = kcs[(b0 + v_) * 127 + jj];
        #pragma unroll
        for (int u = 0; u < 4; u++) wv_[u] = ws[(mm0 + u) * 127 + jj];
        #pragma unroll
        for (int v_ = 0; v_ < 4; v_++)
            #pragma unroll
            for (int u = 0; u < 4; u++) acc[v_][u] += kv[v_] * wv_[u];
    }

    #pragma unroll
    for (int v_ = 0; v_ < 4; v_++)
        #pragma unroll
        for (int u = 0; u < 4; u++)
            g_kpart[((size_t)ksp * 64 + b0 + v_) * NPOS + m0 + mm0 + u] = acc[v_][u];
}

// ---------------------------------------------------------------------------
// Kernel 4: conv2x2 of x as tf32 MMA GEMM (im2col at staging).
// Pn stride 44 (16B-aligned rows; q-dot via LDS.128).
// grid (4 ntile, 64 b), 256 threads. dyn smem = 54400 B, 2 blocks/SM.
// ---------------------------------------------------------------------------
__global__ __launch_bounds__(256, 2) void conv_x_kernel(const float* __restrict__ x,
                                                        const float* __restrict__ wq,
                                                        const float* __restrict__ bq,
                                                        const float* __restrict__ wv,
                                                        const float* __restrict__ bv) {
    extern __shared__ uint32_t cxs[];
    uint32_t* Pn  = cxs;                  // 256*44 = 11264 u32
    uint32_t* wvs = Pn + 11264;           // 64*36  = 2304 u32
    float*    wqc = reinterpret_cast<float*>(wvs + 2304);   // 32

    int ntile = blockIdx.x;
    int b     = blockIdx.y;
    int t     = threadIdx.x;
    int w     = t >> 5;
    int l     = t & 31;
    int g     = l >> 2;
    int tg    = l & 3;
    int mt    = w & 3;
    int half  = w >> 2;

    float acc[16][4];
    #pragma unroll
    for (int nt = 0; nt < 16; nt++)
        #pragma unroll
        for (int u = 0; u < 4; u++) acc[nt][u] = 0.f;
    float qacc = 0.f;

    for (int chunk = 0; chunk < 8; chunk++) {
        int k0  = chunk * 32;
        int ci0 = chunk * 8;
        __syncthreads();
        #pragma unroll
        for (int s = 0; s < 8; s++) {
            int idx = t + s * 256;
            int co = idx >> 5, kl = idx & 31;
            wvs[co * 36 + kl] = tf32r(wv[co * 256 + k0 + kl]);
        }
        if (t < 32) wqc[t] = wq[k0 + t];
        #pragma unroll
        for (int s = 0; s < 8; s++) {
            int idx = t + s * 256;
            int cl  = idx >> 8;
            int rem = idx & 255;
            int r   = rem >> 4;
            int c4  = rem & 15;
            float4 xv = *reinterpret_cast<const float4*>(
                &x[(((size_t)b * 64 + ci0 + cl) * 64 + ntile * 16 + r) * 64 + c4 * 4]);
            int n2 = (r >> 1) * 32 + c4 * 2;
            int kb = cl * 4 + (r & 1) * 2;
            uint2 p0 = make_uint2(tf32r(xv.x), tf32r(xv.y));
            uint2 p1 = make_uint2(tf32r(xv.z), tf32r(xv.w));
            *reinterpret_cast<uint2*>(&Pn[n2 * 44 + kb])       = p0;
            *reinterpret_cast<uint2*>(&Pn[(n2 + 1) * 44 + kb]) = p1;
        }
        __syncthreads();

        // q partial: 8x LDS.128 per thread (16B-aligned rows)
        {
            const uint4* pr4 = reinterpret_cast<const uint4*>(&Pn[t * 44]);
            #pragma unroll
            for (int i = 0; i < 8; i++) {
                uint4 pv4 = pr4[i];
                qacc = fmaf(wqc[4 * i + 0], __uint_as_float(pv4.x), qacc);
                qacc = fmaf(wqc[4 * i + 1], __uint_as_float(pv4.y), qacc);
                qacc = fmaf(wqc[4 * i + 2], __uint_as_float(pv4.z), qacc);
                qacc = fmaf(wqc[4 * i + 3], __uint_as_float(pv4.w), qacc);
            }
        }

        #pragma unroll
        for (int k8 = 0; k8 < 4; k8++) {
            int kk = k8 * 8 + tg;
            const uint32_t* ap = &wvs[(mt * 16 + g) * 36 + kk];
            uint32_t a0 = ap[0];
            uint32_t a1 = ap[8 * 36];
            uint32_t a2 = ap[4];
            uint32_t a3 = ap[8 * 36 + 4];
            #pragma unroll
            for (int nt = 0; nt < 16; nt++) {
                const uint32_t* bp = &Pn[(half * 128 + nt * 8 + g) * 44 + kk];
                mma_tf32(acc[nt][0], acc[nt][1], acc[nt][2], acc[nt][3],
                         a0, a1, a2, a3, bp[0], bp[4]);
            }
        }
    }

    int c0 = mt * 16 + g;
    float bv0 = bv[c0];
    float bv8 = bv[c0 + 8];
    int nb = ntile * 256 + half * 128;
    #pragma unroll
    for (int nt = 0; nt < 16; nt++) {
        int n = nb + nt * 8 + 2 * tg;
        *reinterpret_cast<float2*>(&g_pv[((size_t)b * 64 + c0) * NPOS + n]) =
            make_float2(acc[nt][0] + bv0, acc[nt][1] + bv0);
        *reinterpret_cast<float2*>(&g_pv[((size_t)b * 64 + c0 + 8) * NPOS + n]) =
            make_float2(acc[nt][2] + bv8, acc[nt][3] + bv8);
    }
    g_q[b * NPOS + ntile * 256 + t] = qacc + bq[0];
}

// ---------------------------------------------------------------------------
// Kernel 5: fused split-K k-reduction + softmax + attn write + tf32 MMA GEMM
// + ConvTranspose2d. 256 m-rows/block, grid (4, 64), 256 threads,
// dyn smem = 93184 B.
// Prologue now sums the 9 k-partials + bias itself (identical order to the
// old kreduce) and computes block max/min via shfl (order-independent).
// ---------------------------------------------------------------------------
__global__ __launch_bounds__(256, 2) void attn_kernel(float* __restrict__ attn_out,
                                                      int has_attn,
                                                      const float* __restrict__ bproj,
                                                      const float* __restrict__ bu,
                                                      float* __restrict__ up) {
    extern __shared__ float dsm[];
    float*    ks   = dsm;                                      // [1024]
    float*    sLs  = dsm + 1024;                               // [256]
    float*    offs = dsm + 1280;                               // [256]
    uint32_t* pvs  = reinterpret_cast<uint32_t*>(dsm + 1536);  // [64*68]
    float*    es   = dsm + 1536 + 4352;                        // [256*68]
    uint32_t* outS = reinterpret_cast<uint32_t*>(es);          // alias

    __shared__ float redmax[8], redmin[8];
    __shared__ float bkmax, bkmin;

    const float L2E = 1.4426950408889634f;
    int mt = blockIdx.x;
    int b  = blockIdx.y;
    int m0 = mt * 256;
    int t  = threadIdx.x;
    int w  = t >> 5;
    int l  = t & 31;
    int g  = l >> 2;
    int tg = l & 3;

    // pv prefetch first (independent LDGs; hide the k-reduction under them)
    int pv_c  = t >> 6;
    int pv_nn = t & 63;
    float pvf[16];
    #pragma unroll
    for (int s = 0; s < 16; s++)
        pvf[s] = g_pv[((size_t)b * 64 + (pv_c + s * 4)) * NPOS + pv_nn];

    // fused k-reduction: ks[n] = bproj[n] + sum_ksp g_kpart[ksp][b][n]
    float kmx = __int_as_float(0xFF800000);
    float kmn = __int_as_float(0x7F800000);
    #pragma unroll
    for (int j = 0; j < 4; j++) {
        int n = t + j * 256;
        float s = bproj[n];
        #pragma unroll
        for (int ksp = 0; ksp < 9; ksp++)
            s += g_kpart[((size_t)ksp * 64 + b) * NPOS + n];
        ks[n] = s;
        kmx = fmaxf(kmx, s);
        kmn = fminf(kmn, s);
    }
    #pragma unroll
    for (int d = 16; d > 0; d >>= 1) {
        kmx = fmaxf(kmx, __shfl_xor_sync(0xFFFFFFFF, kmx, d));
        kmn = fminf(kmn, __shfl_xor_sync(0xFFFFFFFF, kmn, d));
    }
    if (l == 0) { redmax[w] = kmx; redmin[w] = kmn; }
    __syncthreads();
    if (t == 0) {
        float mx = redmax[0], mn = redmin[0];
        #pragma unroll
        for (int i = 1; i < 8; i++) {
            mx = fmaxf(mx, redmax[i]);
            mn = fminf(mn, redmin[i]);
        }
        bkmax = mx; bkmin = mn;
    }
    __syncthreads();

    {
        float s   = g_q[b * NPOS + m0 + t] * 0.03125f;   // 1/sqrt(1024)
        float rm  = (s >= 0.f) ? s * bkmax : s * bkmin;
        float sL  = s * L2E;
        float rmL = rm * L2E;
        float p0 = 0.f, p1 = 0.f, p2 = 0.f, p3 = 0.f;
        #pragma unroll 4
        for (int n = 0; n < 1024; n += 4) {
            p0 += ex2f(fmaf(sL, ks[n + 0], -rmL));
            p1 += ex2f(fmaf(sL, ks[n + 1], -rmL));
            p2 += ex2f(fmaf(sL, ks[n + 2], -rmL));
            p3 += ex2f(fmaf(sL, ks[n + 3], -rmL));
        }
        float Z = (p0 + p1) + (p2 + p3);
        sLs[t]  = sL;
        offs[t] = -rmL - lg2f(Z);
    }
    __syncthreads();

    int mbase = w * 32;
    float sl[4], of[4];
    #pragma unroll
    for (int nt = 0; nt < 4; nt++) {
        int mm = mbase + nt * 8 + g;
        sl[nt] = sLs[mm];
        of[nt] = offs[mm];
    }

    float acc[4][4][4];
    #pragma unroll
    for (int ct = 0; ct < 4; ct++)
        #pragma unroll
        for (int nt = 0; nt < 4; nt++)
            #pragma unroll
            for (int u = 0; u < 4; u++) acc[ct][nt][u] = 0.f;

    for (int ch = 0; ch < 16; ch++) {
        int nn0 = ch * 64;
        __syncthreads();
        #pragma unroll
        for (int s = 0; s < 16; s++)
            pvs[(pv_c + s * 4) * 68 + pv_nn] = tf32r(pvf[s]);
        if (ch < 15) {
            int nb2 = nn0 + 64;
            #pragma unroll
            for (int s = 0; s < 16; s++)
                pvf[s] = g_pv[((size_t)b * 64 + (pv_c + s * 4)) * NPOS + nb2 + pv_nn];
        }
        __syncthreads();

        #pragma unroll
        for (int ks8 = 0; ks8 < 8; ks8++) {
            int kk = ks8 * 8 + tg;
            float k0v = ks[nn0 + kk];
            float k4v = ks[nn0 + kk + 4];

            uint32_t afr[4][4];
            #pragma unroll
            for (int ct = 0; ct < 4; ct++) {
                const uint32_t* ap = &pvs[(ct * 16 + g) * 68 + kk];
                afr[ct][0] = ap[0];
                afr[ct][1] = ap[8 * 68];
                afr[ct][2] = ap[4];
                afr[ct][3] = ap[8 * 68 + 4];
            }

            #pragma unroll
            for (int nt = 0; nt < 4; nt++) {
                float e0 = ex2f(fmaf(sl[nt], k0v, of[nt]));
                float e4 = ex2f(fmaf(sl[nt], k4v, of[nt]));
                int ml = mbase + nt * 8 + g;
                es[ml * 68 + kk]     = e0;
                es[ml * 68 + kk + 4] = e4;
                uint32_t b0 = tf32r(e0);
                uint32_t b1 = tf32r(e4);
                #pragma unroll
                for (int ct = 0; ct < 4; ct++)
                    mma_tf32(acc[ct][nt][0], acc[ct][nt][1], acc[ct][nt][2], acc[ct][nt][3],
                             afr[ct][0], afr[ct][1], afr[ct][2], afr[ct][3],
                             b0, b1);
            }
        }

        // warp-private coalesced attn write: own 32 rows, 256 B each
        if (has_attn) {
            __syncwarp();
            float* dst = attn_out + ((size_t)(b * 1024 + m0 + mbase)) * 1024 + nn0 + 2 * l;
            #pragma unroll 8
            for (int r2 = 0; r2 < 32; r2++) {
                float2 val = *reinterpret_cast<const float2*>(&es[(mbase + r2) * 68 + 2 * l]);
                *reinterpret_cast<float2*>(dst + (size_t)r2 * 1024) = val;
            }
        }
    }

    // ---- Epilogue 1: out D-frags -> smem (tf32 bits), layout outS[m][c] ----
    __syncwarp();
    #pragma unroll
    for (int ct = 0; ct < 4; ct++) {
        #pragma unroll
        for (int nt = 0; nt < 4; nt++) {
            int ml = mbase + nt * 8 + 2 * tg;
            int c  = ct * 16 + g;
            outS[ml * 68 + c]           = tf32r(acc[ct][nt][0]);
            outS[(ml + 1) * 68 + c]     = tf32r(acc[ct][nt][1]);
            outS[ml * 68 + c + 8]       = tf32r(acc[ct][nt][2]);
            outS[(ml + 1) * 68 + c + 8] = tf32r(acc[ct][nt][3]);
        }
    }
    __syncthreads();

    // ---- Epilogue 2: up-GEMM ----
    #pragma unroll
    for (int dtl = 0; dtl < 2; dtl++) {
        int dt = w * 2 + dtl;
        uint32_t af[8][4];
        #pragma unroll
        for (int k8 = 0; k8 < 8; k8++) {
            const uint32_t* ap = &g_wuT[(dt * 16 + g) * 64 + k8 * 8 + tg];
            af[k8][0] = ap[0];
            af[k8][1] = ap[8 * 64];
            af[k8][2] = ap[4];
            af[k8][3] = ap[8 * 64 + 4];
        }
        int dab0 = dt * 16 + g;
        int dab1 = dab0 + 8;
        int dd0 = dab0 >> 2, aa0 = (dab0 >> 1) & 1, bb0 = dab0 & 1;
        int dd1 = dab1 >> 2, aa1 = (dab1 >> 1) & 1, bb1 = dab1 & 1;
        float bud0 = __ldg(&bu[dd0]);
        float bud1 = __ldg(&bu[dd1]);

        for (int mt2 = 0; mt2 < 32; mt2++) {
            float e0 = 0.f, e1 = 0.f, e2 = 0.f, e3 = 0.f;
            #pragma unroll
            for (int k8 = 0; k8 < 8; k8++) {
                const uint32_t* bp = &outS[(mt2 * 8 + g) * 68 + k8 * 8 + tg];
                mma_tf32(e0, e1, e2, e3,
                         af[k8][0], af[k8][1], af[k8][2], af[k8][3],
                         bp[0], bp[4]);
            }
            int mg = m0 + mt2 * 8 + 2 * tg;
            int i = mg >> 5, j = mg & 31;
            size_t a0 = (((size_t)(b * 64 + dd0)) * 64 + 2 * i + aa0) * 64 + 2 * j + bb0;
            size_t a1 = (((size_t)(b * 64 + dd1)) * 64 + 2 * i + aa1) * 64 + 2 * j + bb1;
            up[a0]     = e0 + bud0;
            up[a0 + 2] = e1 + bud0;
            up[a1]     = e2 + bud1;
            up[a1 + 2] = e3 + bud1;
        }
    }
}

// ---------------------------------------------------------------------------
extern "C" void kernel_launch(void* const* d_in, const int* in_sizes, int n_in,
                              void* d_out, int out_size) {
    const float* x     = (const float*)d_in[0];
    const float* v     = (const float*)d_in[1];
    const float* wq    = (const float*)d_in[2];
    const float* bq    = (const float*)d_in[3];
    const float* wk    = (const float*)d_in[4];
    const float* bk    = (const float*)d_in[5];
    const float* wv    = (const float*)d_in[6];
    const float* bv    = (const float*)d_in[7];
    const float* wu    = (const float*)d_in[8];
    const float* bu    = (const float*)d_in[9];
    const float* wproj = (const float*)d_in[10];
    const float* bproj = (const float*)d_in[11];

    float* up_out   = (float*)d_out;
    int has_attn    = (out_size > UP_ELEMS) ? 1 : 0;
    float* attn_out = up_out + UP_ELEMS;

    cudaFuncSetAttribute(kproj_part_kernel, cudaFuncAttributeMaxDynamicSharedMemorySize, 65024);
    cudaFuncSetAttribute(conv_x_kernel,     cudaFuncAttributeMaxDynamicSharedMemorySize, 54400);
    cudaFuncSetAttribute(attn_kernel,       cudaFuncAttributeMaxDynamicSharedMemorySize, 93184);

    static cudaStream_t s1 = []() {
        cudaStream_t s;
        cudaStreamCreateWithFlags(&s, cudaStreamNonBlocking);
        return s;
    }();
    static cudaEvent_t evFork = []() {
        cudaEvent_t e;
        cudaEventCreateWithFlags(&e, cudaEventDisableTiming);
        return e;
    }();
    static cudaEvent_t evJoin = []() {
        cudaEvent_t e;
        cudaEventCreateWithFlags(&e, cudaEventDisableTiming);
        return e;
    }();

    cudaEventRecord(evFork, 0);
    cudaStreamWaitEvent(s1, evFork, 0);

    // Branch A (side stream): conv_x
    conv_x_kernel<<<dim3(4, 64), 256, 54400, s1>>>(x, wq, bq, wv, bv);

    // Branch B (main stream): conv_v -> kproj_part
    conv_v_kernel<<<dim3(42, 64), 256>>>(v, wk, bk, wu);
    kproj_part_kernel<<<dim3(16, 9), 256, 65024>>>(wproj);

    cudaEventRecord(evJoin, s1);
    cudaStreamWaitEvent(0, evJoin, 0);

    attn_kernel<<<dim3(4, 64), 256, 93184>>>(attn_out, has_attn, bproj, bu, up_out);
}

// round 17
// speedup vs baseline: 1.1474x; 1.0502x over previous
#include <cuda_runtime.h>
#include <cuda_bf16.h>
#include <cstdint>

// Problem constants
#define BATCH 64
#define CH    64
#define HH    64
#define WW    64
#define NPOS  1024        // 32*32
#define KPIN  1134        // 42*27 = 9*126
#define KPOUT 1024
#define UP_ELEMS (BATCH*CH*HH*WW)          // 16777216
#define ATTN_ELEMS (BATCH*NPOS*NPOS)       // 67108864

// Scratch (device globals; no allocation)
__device__ float    g_pv[BATCH * CH * NPOS];   // [b][c][n]
__device__ float    g_q[BATCH * NPOS];
__device__ float    g_kc[BATCH * KPIN];
__device__ float    g_kpart[9 * BATCH * NPOS]; // split-K partials [ks][b][m]
__device__ uint32_t g_wuT[256 * 64];           // tf32 bits, [dab][c]

typedef unsigned long long ull;

__device__ __forceinline__ float ex2f(float x) {
    float y;
    asm("ex2.approx.ftz.f32 %0, %1;" : "=f"(y) : "f"(x));
    return y;
}
__device__ __forceinline__ float lg2f(float x) {
    float y;
    asm("lg2.approx.ftz.f32 %0, %1;" : "=f"(y) : "f"(x));
    return y;
}
__device__ __forceinline__ uint32_t tf32r(float x) {
    uint32_t r;
    asm("cvt.rna.tf32.f32 %0, %1;" : "=r"(r) : "f"(x));
    return r;
}
__device__ __forceinline__ void mma_tf32(float& d0, float& d1, float& d2, float& d3,
                                         uint32_t a0, uint32_t a1, uint32_t a2, uint32_t a3,
                                         uint32_t b0, uint32_t b1) {
    asm("mma.sync.aligned.m16n8k8.row.col.f32.tf32.tf32.f32 "
        "{%0,%1,%2,%3}, {%4,%5,%6,%7}, {%8,%9}, {%0,%1,%2,%3};"
        : "+f"(d0), "+f"(d1), "+f"(d2), "+f"(d3)
        : "r"(a0), "r"(a1), "r"(a2), "r"(a3), "r"(b0), "r"(b1));
}

// ---------------------------------------------------------------------------
// Kernel 1: conv2x2(v, wk) -> g_kc[b][ii*27+jj]
// Blocks with ii==0 also stage g_wuT (tf32 transpose of wu).
// ---------------------------------------------------------------------------
__global__ __launch_bounds__(256) void conv_v_kernel(const float* __restrict__ v,
                                                     const float* __restrict__ wk,
                                                     const float* __restrict__ bk,
                                                     const float* __restrict__ wu) {
    __shared__ float vs[64 * 2 * 54];
    __shared__ float wks[256];
    __shared__ float part[8][28];
    int ii = blockIdx.x;
    int b  = blockIdx.y;
    int t  = threadIdx.x;

    if (ii == 0) {
        int idx = b * 256 + t;          // 0..16383, each exactly once
        int dab = idx & 255;
        int c   = idx >> 8;
        g_wuT[dab * 64 + c] = tf32r(wu[c * 256 + dab]);
    }

    wks[t] = wk[t];
    for (int idx = t; idx < 64 * 2 * 54; idx += 256) {
        int c   = idx / 108;
        int rem = idx - c * 108;
        int a   = rem / 54;
        int col = rem - a * 54;
        vs[idx] = v[((b * 64 + c) * 84 + (2 * ii + a)) * 54 + col];
    }
    __syncthreads();

    if (t < 216) {
        int jj = t % 27;
        int cg = t / 27;
        float acc = 0.f;
        #pragma unroll
        for (int cc = 0; cc < 8; cc++) {
            int c = cg * 8 + cc;
            #pragma unroll
            for (int a = 0; a < 2; a++) {
                float x0 = vs[(c * 2 + a) * 54 + 2 * jj + 0];
                float x1 = vs[(c * 2 + a) * 54 + 2 * jj + 1];
                acc += x0 * wks[c * 4 + a * 2 + 0] + x1 * wks[c * 4 + a * 2 + 1];
            }
        }
        part[cg][jj] = acc;
    }
    __syncthreads();
    if (t < 27) {
        float s = bk[0];
        #pragma unroll
        for (int cg = 0; cg < 8; cg++) s += part[cg][t];
        g_kc[b * KPIN + ii * 27 + t] = s;
    }
}

// ---------------------------------------------------------------------------
// Kernel 2: split-K partial GEMM via tf32 MMA.
// grid (16 m-tiles, 9 k-splits), 256 threads = 8 warps, dyn smem = 67584 B.
// Warp w: b-tile (w&3)*16, m-half (w>>2)*32 (4 n8-tiles). K padded 126->128.
// g_kpart[ksp][b][m] = sum_{k in split} kc[b][k] * wproj[m][k]
// ---------------------------------------------------------------------------
__global__ __launch_bounds__(256) void kproj_part_kernel(const float* __restrict__ wproj) {
    extern __shared__ uint32_t km[];
    uint32_t* kcs = km;             // [64][132]
    uint32_t* ws  = km + 64 * 132;  // [64][132]
    int mt  = blockIdx.x;
    int ksp = blockIdx.y;
    int m0  = mt * 64;
    int k0  = ksp * 126;
    int t   = threadIdx.x;
    int w   = t >> 5;
    int l   = t & 31;
    int g   = l >> 2;
    int tg  = l & 3;

    // stage kc & wproj tiles (tf32 bits), zero-pad cols 126..127
    #pragma unroll
    for (int s = 0; s < 32; s++) {
        int idx = t + s * 256;
        int row = idx >> 7;
        int col = idx & 127;
        uint32_t kv = 0, wv = 0;
        if (col < 126) {
            kv = tf32r(g_kc[row * KPIN + k0 + col]);
            wv = tf32r(wproj[(size_t)(m0 + row) * KPIN + k0 + col]);
        }
        kcs[row * 132 + col] = kv;
        ws[row * 132 + col]  = wv;
    }
    __syncthreads();

    int bt = w & 3;       // b-tile (16 rows)
    int wm = w >> 2;      // m-half (32 cols)

    float acc[4][4];
    #pragma unroll
    for (int nt = 0; nt < 4; nt++)
        #pragma unroll
        for (int u = 0; u < 4; u++) acc[nt][u] = 0.f;

    #pragma unroll
    for (int k8 = 0; k8 < 16; k8++) {
        int kk = k8 * 8 + tg;
        const uint32_t* ap = &kcs[(bt * 16 + g) * 132 + kk];
        uint32_t a0 = ap[0];
        uint32_t a1 = ap[8 * 132];
        uint32_t a2 = ap[4];
        uint32_t a3 = ap[8 * 132 + 4];
        #pragma unroll
        for (int nt = 0; nt < 4; nt++) {
            const uint32_t* bp = &ws[(wm * 32 + nt * 8 + g) * 132 + kk];
            mma_tf32(acc[nt][0], acc[nt][1], acc[nt][2], acc[nt][3],
                     a0, a1, a2, a3, bp[0], bp[4]);
        }
    }

    #pragma unroll
    for (int nt = 0; nt < 4; nt++) {
        int m    = m0 + wm * 32 + nt * 8 + 2 * tg;
        int b_lo = bt * 16 + g;
        *reinterpret_cast<float2*>(
            &g_kpart[((size_t)ksp * 64 + b_lo) * NPOS + m]) =
            make_float2(acc[nt][0], acc[nt][1]);
        *reinterpret_cast<float2*>(
            &g_kpart[((size_t)ksp * 64 + b_lo + 8) * NPOS + m]) =
            make_float2(acc[nt][2], acc[nt][3]);
    }
}

// ---------------------------------------------------------------------------
// Kernel 4: conv2x2 of x as tf32 MMA GEMM (im2col at staging).
// Pn stride 44 (16B-aligned rows; q-dot via LDS.128).
// grid (4 ntile, 64 b), 256 threads. dyn smem = 54400 B, 2 blocks/SM.
// ---------------------------------------------------------------------------
__global__ __launch_bounds__(256, 2) void conv_x_kernel(const float* __restrict__ x,
                                                        const float* __restrict__ wq,
                                                        const float* __restrict__ bq,
                                                        const float* __restrict__ wv,
                                                        const float* __restrict__ bv) {
    extern __shared__ uint32_t cxs[];
    uint32_t* Pn  = cxs;                  // 256*44 = 11264 u32
    uint32_t* wvs = Pn + 11264;           // 64*36  = 2304 u32
    float*    wqc = reinterpret_cast<float*>(wvs + 2304);   // 32

    int ntile = blockIdx.x;
    int b     = blockIdx.y;
    int t     = threadIdx.x;
    int w     = t >> 5;
    int l     = t & 31;
    int g     = l >> 2;
    int tg    = l & 3;
    int mt    = w & 3;
    int half  = w >> 2;

    float acc[16][4];
    #pragma unroll
    for (int nt = 0; nt < 16; nt++)
        #pragma unroll
        for (int u = 0; u < 4; u++) acc[nt][u] = 0.f;
    float qacc = 0.f;

    for (int chunk = 0; chunk < 8; chunk++) {
        int k0  = chunk * 32;
        int ci0 = chunk * 8;
        __syncthreads();
        #pragma unroll
        for (int s = 0; s < 8; s++) {
            int idx = t + s * 256;
            int co = idx >> 5, kl = idx & 31;
            wvs[co * 36 + kl] = tf32r(wv[co * 256 + k0 + kl]);
        }
        if (t < 32) wqc[t] = wq[k0 + t];
        #pragma unroll
        for (int s = 0; s < 8; s++) {
            int idx = t + s * 256;
            int cl  = idx >> 8;
            int rem = idx & 255;
            int r   = rem >> 4;
            int c4  = rem & 15;
            float4 xv = *reinterpret_cast<const float4*>(
                &x[(((size_t)b * 64 + ci0 + cl) * 64 + ntile * 16 + r) * 64 + c4 * 4]);
            int n2 = (r >> 1) * 32 + c4 * 2;
            int kb = cl * 4 + (r & 1) * 2;
            uint2 p0 = make_uint2(tf32r(xv.x), tf32r(xv.y));
            uint2 p1 = make_uint2(tf32r(xv.z), tf32r(xv.w));
            *reinterpret_cast<uint2*>(&Pn[n2 * 44 + kb])       = p0;
            *reinterpret_cast<uint2*>(&Pn[(n2 + 1) * 44 + kb]) = p1;
        }
        __syncthreads();

        // q partial: 8x LDS.128 per thread (16B-aligned rows)
        {
            const uint4* pr4 = reinterpret_cast<const uint4*>(&Pn[t * 44]);
            #pragma unroll
            for (int i = 0; i < 8; i++) {
                uint4 pv4 = pr4[i];
                qacc = fmaf(wqc[4 * i + 0], __uint_as_float(pv4.x), qacc);
                qacc = fmaf(wqc[4 * i + 1], __uint_as_float(pv4.y), qacc);
                qacc = fmaf(wqc[4 * i + 2], __uint_as_float(pv4.z), qacc);
                qacc = fmaf(wqc[4 * i + 3], __uint_as_float(pv4.w), qacc);
            }
        }

        #pragma unroll
        for (int k8 = 0; k8 < 4; k8++) {
            int kk = k8 * 8 + tg;
            const uint32_t* ap = &wvs[(mt * 16 + g) * 36 + kk];
            uint32_t a0 = ap[0];
            uint32_t a1 = ap[8 * 36];
            uint32_t a2 = ap[4];
            uint32_t a3 = ap[8 * 36 + 4];
            #pragma unroll
            for (int nt = 0; nt < 16; nt++) {
                const uint32_t* bp = &Pn[(half * 128 + nt * 8 + g) * 44 + kk];
                mma_tf32(acc[nt][0], acc[nt][1], acc[nt][2], acc[nt][3],
                         a0, a1, a2, a3, bp[0], bp[4]);
            }
        }
    }

    int c0 = mt * 16 + g;
    float bv0 = bv[c0];
    float bv8 = bv[c0 + 8];
    int nb = ntile * 256 + half * 128;
    #pragma unroll
    for (int nt = 0; nt < 16; nt++) {
        int n = nb + nt * 8 + 2 * tg;
        *reinterpret_cast<float2*>(&g_pv[((size_t)b * 64 + c0) * NPOS + n]) =
            make_float2(acc[nt][0] + bv0, acc[nt][1] + bv0);
        *reinterpret_cast<float2*>(&g_pv[((size_t)b * 64 + c0 + 8) * NPOS + n]) =
            make_float2(acc[nt][2] + bv8, acc[nt][3] + bv8);
    }
    g_q[b * NPOS + ntile * 256 + t] = qacc + bq[0];
}

// ---------------------------------------------------------------------------
// Kernel 5: fused split-K k-reduction + softmax + attn write + tf32 MMA GEMM
// + ConvTranspose2d. 256 m-rows/block, grid (4, 64), 256 threads,
// dyn smem = 93184 B.
// ---------------------------------------------------------------------------
__global__ __launch_bounds__(256, 2) void attn_kernel(float* __restrict__ attn_out,
                                                      int has_attn,
                                                      const float* __restrict__ bproj,
                                                      const float* __restrict__ bu,
                                                      float* __restrict__ up) {
    extern __shared__ float dsm[];
    float*    ks   = dsm;                                      // [1024]
    float*    sLs  = dsm + 1024;                               // [256]
    float*    offs = dsm + 1280;                               // [256]
    uint32_t* pvs  = reinterpret_cast<uint32_t*>(dsm + 1536);  // [64*68]
    float*    es   = dsm + 1536 + 4352;                        // [256*68]
    uint32_t* outS = reinterpret_cast<uint32_t*>(es);          // alias

    __shared__ float redmax[8], redmin[8];
    __shared__ float bkmax, bkmin;

    const float L2E = 1.4426950408889634f;
    int mt = blockIdx.x;
    int b  = blockIdx.y;
    int m0 = mt * 256;
    int t  = threadIdx.x;
    int w  = t >> 5;
    int l  = t & 31;
    int g  = l >> 2;
    int tg = l & 3;

    // prefetch pv + q (independent LDGs; hide k-reduction & pass-1 under them)
    int pv_c  = t >> 6;
    int pv_nn = t & 63;
    float pvf[16];
    #pragma unroll
    for (int s = 0; s < 16; s++)
        pvf[s] = g_pv[((size_t)b * 64 + (pv_c + s * 4)) * NPOS + pv_nn];
    float qv = g_q[b * NPOS + m0 + t];

    // fused k-reduction: ks[n] = bproj[n] + sum_ksp g_kpart[ksp][b][n]
    float kmx = __int_as_float(0xFF800000);
    float kmn = __int_as_float(0x7F800000);
    #pragma unroll
    for (int j = 0; j < 4; j++) {
        int n = t + j * 256;
        float s = bproj[n];
        #pragma unroll
        for (int ksp = 0; ksp < 9; ksp++)
            s += g_kpart[((size_t)ksp * 64 + b) * NPOS + n];
        ks[n] = s;
        kmx = fmaxf(kmx, s);
        kmn = fminf(kmn, s);
    }
    #pragma unroll
    for (int d = 16; d > 0; d >>= 1) {
        kmx = fmaxf(kmx, __shfl_xor_sync(0xFFFFFFFF, kmx, d));
        kmn = fminf(kmn, __shfl_xor_sync(0xFFFFFFFF, kmn, d));
    }
    if (l == 0) { redmax[w] = kmx; redmin[w] = kmn; }
    __syncthreads();
    if (t == 0) {
        float mx = redmax[0], mn = redmin[0];
        #pragma unroll
        for (int i = 1; i < 8; i++) {
            mx = fmaxf(mx, redmax[i]);
            mn = fminf(mn, redmin[i]);
        }
        bkmax = mx; bkmin = mn;
    }
    __syncthreads();

    {
        float s   = qv * 0.03125f;   // 1/sqrt(1024)
        float rm  = (s >= 0.f) ? s * bkmax : s * bkmin;
        float sL  = s * L2E;
        float rmL = rm * L2E;
        float p0 = 0.f, p1 = 0.f, p2 = 0.f, p3 = 0.f;
        #pragma unroll 4
        for (int n = 0; n < 1024; n += 4) {
            p0 += ex2f(fmaf(sL, ks[n + 0], -rmL));
            p1 += ex2f(fmaf(sL, ks[n + 1], -rmL));
            p2 += ex2f(fmaf(sL, ks[n + 2], -rmL));
            p3 += ex2f(fmaf(sL, ks[n + 3], -rmL));
        }
        float Z = (p0 + p1) + (p2 + p3);
        sLs[t]  = sL;
        offs[t] = -rmL - lg2f(Z);
    }
    __syncthreads();

    int mbase = w * 32;
    float sl[4], of[4];
    #pragma unroll
    for (int nt = 0; nt < 4; nt++) {
        int mm = mbase + nt * 8 + g;
        sl[nt] = sLs[mm];
        of[nt] = offs[mm];
    }

    float acc[4][4][4];
    #pragma unroll
    for (int ct = 0; ct < 4; ct++)
        #pragma unroll
        for (int nt = 0; nt < 4; nt++)
            #pragma unroll
            for (int u = 0; u < 4; u++) acc[ct][nt][u] = 0.f;

    for (int ch = 0; ch < 16; ch++) {
        int nn0 = ch * 64;
        __syncthreads();
        #pragma unroll
        for (int s = 0; s < 16; s++)
            pvs[(pv_c + s * 4) * 68 + pv_nn] = tf32r(pvf[s]);
        if (ch < 15) {
            int nb2 = nn0 + 64;
            #pragma unroll
            for (int s = 0; s < 16; s++)
                pvf[s] = g_pv[((size_t)b * 64 + (pv_c + s * 4)) * NPOS + nb2 + pv_nn];
        }
        __syncthreads();

        #pragma unroll
        for (int ks8 = 0; ks8 < 8; ks8++) {
            int kk = ks8 * 8 + tg;
            float k0v = ks[nn0 + kk];
            float k4v = ks[nn0 + kk + 4];

            uint32_t afr[4][4];
            #pragma unroll
            for (int ct = 0; ct < 4; ct++) {
                const uint32_t* ap = &pvs[(ct * 16 + g) * 68 + kk];
                afr[ct][0] = ap[0];
                afr[ct][1] = ap[8 * 68];
                afr[ct][2] = ap[4];
                afr[ct][3] = ap[8 * 68 + 4];
            }

            #pragma unroll
            for (int nt = 0; nt < 4; nt++) {
                float e0 = ex2f(fmaf(sl[nt], k0v, of[nt]));
                float e4 = ex2f(fmaf(sl[nt], k4v, of[nt]));
                int ml = mbase + nt * 8 + g;
                es[ml * 68 + kk]     = e0;
                es[ml * 68 + kk + 4] = e4;
                uint32_t b0 = tf32r(e0);
                uint32_t b1 = tf32r(e4);
                #pragma unroll
                for (int ct = 0; ct < 4; ct++)
                    mma_tf32(acc[ct][nt][0], acc[ct][nt][1], acc[ct][nt][2], acc[ct][nt][3],
                             afr[ct][0], afr[ct][1], afr[ct][2], afr[ct][3],
                             b0, b1);
            }
        }

        // warp-private coalesced attn write: own 32 rows, 256 B each
        if (has_attn) {
            __syncwarp();
            float* dst = attn_out + ((size_t)(b * 1024 + m0 + mbase)) * 1024 + nn0 + 2 * l;
            #pragma unroll 8
            for (int r2 = 0; r2 < 32; r2++) {
                float2 val = *reinterpret_cast<const float2*>(&es[(mbase + r2) * 68 + 2 * l]);
                *reinterpret_cast<float2*>(dst + (size_t)r2 * 1024) = val;
            }
        }
    }

    // ---- Epilogue 1: out D-frags -> smem (tf32 bits), layout outS[m][c] ----
    __syncwarp();
    #pragma unroll
    for (int ct = 0; ct < 4; ct++) {
        #pragma unroll
        for (int nt = 0; nt < 4; nt++) {
            int ml = mbase + nt * 8 + 2 * tg;
            int c  = ct * 16 + g;
            outS[ml * 68 + c]           = tf32r(acc[ct][nt][0]);
            outS[(ml + 1) * 68 + c]     = tf32r(acc[ct][nt][1]);
            outS[ml * 68 + c + 8]       = tf32r(acc[ct][nt][2]);
            outS[(ml + 1) * 68 + c + 8] = tf32r(acc[ct][nt][3]);
        }
    }
    __syncthreads();

    // ---- Epilogue 2: up-GEMM ----
    #pragma unroll
    for (int dtl = 0; dtl < 2; dtl++) {
        int dt = w * 2 + dtl;
        uint32_t af[8][4];
        #pragma unroll
        for (int k8 = 0; k8 < 8; k8++) {
            const uint32_t* ap = &g_wuT[(dt * 16 + g) * 64 + k8 * 8 + tg];
            af[k8][0] = ap[0];
            af[k8][1] = ap[8 * 64];
            af[k8][2] = ap[4];
            af[k8][3] = ap[8 * 64 + 4];
        }
        int dab0 = dt * 16 + g;
        int dab1 = dab0 + 8;
        int dd0 = dab0 >> 2, aa0 = (dab0 >> 1) & 1, bb0 = dab0 & 1;
        int dd1 = dab1 >> 2, aa1 = (dab1 >> 1) & 1, bb1 = dab1 & 1;
        float bud0 = __ldg(&bu[dd0]);
        float bud1 = __ldg(&bu[dd1]);

        for (int mt2 = 0; mt2 < 32; mt2++) {
            float e0 = 0.f, e1 = 0.f, e2 = 0.f, e3 = 0.f;
            #pragma unroll
            for (int k8 = 0; k8 < 8; k8++) {
                const uint32_t* bp = &outS[(mt2 * 8 + g) * 68 + k8 * 8 + tg];
                mma_tf32(e0, e1, e2, e3,
                         af[k8][0], af[k8][1], af[k8][2], af[k8][3],
                         bp[0], bp[4]);
            }
            int mg = m0 + mt2 * 8 + 2 * tg;
            int i = mg >> 5, j = mg & 31;
            size_t a0 = (((size_t)(b * 64 + dd0)) * 64 + 2 * i + aa0) * 64 + 2 * j + bb0;
            size_t a1 = (((size_t)(b * 64 + dd1)) * 64 + 2 * i + aa1) * 64 + 2 * j + bb1;
            up[a0]     = e0 + bud0;
            up[a0 + 2] = e1 + bud0;
            up[a1]     = e2 + bud1;
            up[a1 + 2] = e3 + bud1;
        }
    }
}

// ---------------------------------------------------------------------------
extern "C" void kernel_launch(void* const* d_in, const int* in_sizes, int n_in,
                              void* d_out, int out_size) {
    const float* x     = (const float*)d_in[0];
    const float* v     = (const float*)d_in[1];
    const float* wq    = (const float*)d_in[2];
    const float* bq    = (const float*)d_in[3];
    const float* wk    = (const float*)d_in[4];
    const float* bk    = (const float*)d_in[5];
    const float* wv    = (const float*)d_in[6];
    const float* bv    = (const float*)d_in[7];
    const float* wu    = (const float*)d_in[8];
    const float* bu    = (const float*)d_in[9];
    const float* wproj = (const float*)d_in[10];
    const float* bproj = (const float*)d_in[11];

    float* up_out   = (float*)d_out;
    int has_attn    = (out_size > UP_ELEMS) ? 1 : 0;
    float* attn_out = up_out + UP_ELEMS;

    cudaFuncSetAttribute(kproj_part_kernel, cudaFuncAttributeMaxDynamicSharedMemorySize, 67584);
    cudaFuncSetAttribute(conv_x_kernel,     cudaFuncAttributeMaxDynamicSharedMemorySize, 54400);
    cudaFuncSetAttribute(attn_kernel,       cudaFuncAttributeMaxDynamicSharedMemorySize, 93184);

    static cudaStream_t s1 = []() {
        cudaStream_t s;
        cudaStreamCreateWithFlags(&s, cudaStreamNonBlocking);
        return s;
    }();
    static cudaEvent_t evFork = []() {
        cudaEvent_t e;
        cudaEventCreateWithFlags(&e, cudaEventDisableTiming);
        return e;
    }();
    static cudaEvent_t evJoin = []() {
        cudaEvent_t e;
        cudaEventCreateWithFlags(&e, cudaEventDisableTiming);
        return e;
    }();

    cudaEventRecord(evFork, 0);
    cudaStreamWaitEvent(s1, evFork, 0);

    // Branch A (side stream): conv_x
    conv_x_kernel<<<dim3(4, 64), 256, 54400, s1>>>(x, wq, bq, wv, bv);

    // Branch B (main stream): conv_v -> kproj_part (tf32 MMA)
    conv_v_kernel<<<dim3(42, 64), 256>>>(v, wk, bk, wu);
    kproj_part_kernel<<<dim3(16, 9), 256, 67584>>>(wproj);

    cudaEventRecord(evJoin, s1);
    cudaStreamWaitEvent(0, evJoin, 0);

    attn_kernel<<<dim3(4, 64), 256, 93184>>>(attn_out, has_attn, bproj, bu, up_out);
}